// round 10
// baseline (speedup 1.0000x reference)
#include <cuda_runtime.h>
#include <cuda_bf16.h>
#include <stdint.h>
#include <math.h>

#define BB 4
#define TT 1024
#define CC 1024
#define HH 16
#define HD 64
#define NEL (BB*TT*CC)          // 4194304
#define NW  (CC*CC)             // 1048576

// ---------------- scratch (device globals: allocation-free) ----------------
__device__ __nv_bfloat16 g_inh[3][NEL], g_inl[3][NEL];   // split query,key,value (row-major)
__device__ __nv_bfloat16 g_Wh[4][NW],  g_Wl[4][NW];      // split Wq,Wk,Wv,Wo (row-major)
__device__ unsigned g_qfh[NEL/2], g_qfl[NEL/2];          // proj q (x8) bf16 A-frags
__device__ unsigned g_kfh[NEL/2], g_kfl[NEL/2];          // proj k bf16 B-frags
__device__ unsigned g_vtf[NEL];                          // proj v tf32 B-frags
__device__ unsigned g_qrf[NEL];                          // raw q x8 tf32 A-frags
__device__ unsigned g_rtf[32*4096];                      // relpad tf32 B-frag tiles
__device__ __nv_bfloat16 g_ctxh[NEL], g_ctxl[NEL];       // attention out, split row-major

// ---------------- helpers ----------------
__device__ __forceinline__ unsigned f2tf32(float x) {
    unsigned u;
    asm("cvt.rna.tf32.f32 %0, %1;" : "=r"(u) : "f"(x));
    return u;
}
__device__ __forceinline__ void mma_tf32(float4& c, const uint4& a, const uint2& b) {
    asm volatile(
        "mma.sync.aligned.m16n8k8.row.col.f32.tf32.tf32.f32 "
        "{%0,%1,%2,%3}, {%4,%5,%6,%7}, {%8,%9}, {%0,%1,%2,%3};"
        : "+f"(c.x), "+f"(c.y), "+f"(c.z), "+f"(c.w)
        : "r"(a.x), "r"(a.y), "r"(a.z), "r"(a.w), "r"(b.x), "r"(b.y));
}
__device__ __forceinline__ void mma_bf16(float4& c, const uint4& a, const uint2& b) {
    asm volatile(
        "mma.sync.aligned.m16n8k16.row.col.f32.bf16.bf16.f32 "
        "{%0,%1,%2,%3}, {%4,%5,%6,%7}, {%8,%9}, {%0,%1,%2,%3};"
        : "+f"(c.x), "+f"(c.y), "+f"(c.z), "+f"(c.w)
        : "r"(a.x), "r"(a.y), "r"(a.z), "r"(a.w), "r"(b.x), "r"(b.y));
}
__device__ __forceinline__ void split_pair(float x, float y, unsigned& hi, unsigned& lo) {
    __nv_bfloat16 hx = __float2bfloat16(x), hy = __float2bfloat16(y);
    __nv_bfloat162 H; H.x = hx; H.y = hy;
    __nv_bfloat162 L;
    L.x = __float2bfloat16(x - __bfloat162float(hx));
    L.y = __float2bfloat16(y - __bfloat162float(hy));
    hi = *reinterpret_cast<unsigned*>(&H);
    lo = *reinterpret_cast<unsigned*>(&L);
}

// ---------------- convert A: split q/k/v row-major + qraw tf32 A-frags ----------------
__global__ void convA(const float* __restrict__ q, const float* __restrict__ k,
                      const float* __restrict__ v,
                      __nv_bfloat16* __restrict__ inh, __nv_bfloat16* __restrict__ inl,
                      unsigned* __restrict__ qrf)
{
    int blk = blockIdx.x;
    int arr = blk >> 12;
    int i = ((blk & 4095) << 8) + threadIdx.x;
    const float* src = arr == 0 ? q : (arr == 1 ? k : v);
    float4 v4 = ((const float4*)src)[i];
    unsigned h0, l0, h1, l1;
    split_pair(v4.x, v4.y, h0, l0);
    split_pair(v4.z, v4.w, h1, l1);
    ((uint2*)(inh + (size_t)arr * NEL))[i] = make_uint2(h0, h1);
    ((uint2*)(inl + (size_t)arr * NEL))[i] = make_uint2(l0, l1);
    if (arr == 0) {
        int e = i * 4;
        int m = e >> 10, ch = e & 1023;
        int hh_ = ch >> 6, d = ch & 63;
        int b_ = m >> 10, tt = (m >> 7) & 7, mr = m & 127;
        size_t blko = ((size_t)((b_ * 8 + tt) * 16 + hh_)) << 13;
        int base = ((d >> 3) * 8 + (mr >> 4)) * 128 + (mr & 7) * 16
                 + ((mr >> 3) & 1) + 2 * ((d >> 2) & 1);
        qrf[blko + base +  0] = f2tf32(8.f * v4.x);
        qrf[blko + base +  4] = f2tf32(8.f * v4.y);
        qrf[blko + base +  8] = f2tf32(8.f * v4.z);
        qrf[blko + base + 12] = f2tf32(8.f * v4.w);
    }
}

// ---------------- convert W: split 4 weights + relpad tf32 B-frag tiles ----------------
__global__ void convW(const float* __restrict__ Wq, const float* __restrict__ Wk,
                      const float* __restrict__ Wv, const float* __restrict__ Wo,
                      const float* __restrict__ rel_emb,
                      __nv_bfloat16* __restrict__ Wh, __nv_bfloat16* __restrict__ Wl,
                      unsigned* __restrict__ rtf)
{
    int blk = blockIdx.x;
    if (blk < 4096) {
        int arr = blk >> 10;
        int i = ((blk & 1023) << 8) + threadIdx.x;
        const float* src = arr == 0 ? Wq : (arr == 1 ? Wk : (arr == 2 ? Wv : Wo));
        float4 v4 = ((const float4*)src)[i];
        unsigned h0, l0, h1, l1;
        split_pair(v4.x, v4.y, h0, l0);
        split_pair(v4.z, v4.w, h1, l1);
        ((uint2*)(Wh + (size_t)arr * NW))[i] = make_uint2(h0, h1);
        ((uint2*)(Wl + (size_t)arr * NW))[i] = make_uint2(l0, l1);
    } else {
        int e = ((blk - 4096) << 8) + threadIdx.x;
        int tt = e >> 12, rem = e & 4095;
        int ul = rem >> 6, d = rem & 63;
        int u = tt * 64 + ul;
        int src = u - 24;
        src = src < 0 ? 0 : (src > 1998 ? 1998 : src);
        int addr = tt * 4096 + ((d >> 3) * 8 + (ul >> 3)) * 64
                 + ((ul & 7) * 4 + (d & 3)) * 2 + ((d >> 2) & 1);
        rtf[addr] = f2tf32(rel_emb[src * HD + d]);
    }
}

// ========== bf16 3-term NT GEMM (round-6 config — known best) ==========
// MODE 0: fp32 row-major. MODE 1: Q bf16 A-frags hi/lo. MODE 2: K bf16 B-frags hi/lo.
// MODE 3: V tf32 B-frags.
template <int MODE>
__global__ __launch_bounds__(256)
void gemm2(const __nv_bfloat16* __restrict__ Ah, const __nv_bfloat16* __restrict__ Al,
           const __nv_bfloat16* __restrict__ Bh, const __nv_bfloat16* __restrict__ Bl,
           const float* __restrict__ bias, void* __restrict__ o0, void* __restrict__ o1,
           int M, int N, int K, float scale)
{
    __shared__ unsigned As_h[2][1024], As_l[2][1024];
    __shared__ unsigned Bs_h[2][1024], Bs_l[2][1024];

    const int tid = threadIdx.x;
    const int lane = tid & 31;
    const int warp = tid >> 5;
    const int wrow = warp & 1, wcol = warp >> 1;
    const int bm = blockIdx.y * 128, bn = blockIdx.x * 128;
    const int r2 = tid >> 1, c2 = tid & 1;

    float4 acc[4][4];
#pragma unroll
    for (int i = 0; i < 4; i++)
#pragma unroll
        for (int j = 0; j < 4; j++) acc[i][j] = make_float4(0.f, 0.f, 0.f, 0.f);

    uint4 sah, sal, sbh, sbl;
    sah = *(const uint4*)(Ah + (size_t)(bm + r2) * K + c2 * 8);
    sal = *(const uint4*)(Al + (size_t)(bm + r2) * K + c2 * 8);
    sbh = *(const uint4*)(Bh + (size_t)(bn + r2) * K + c2 * 8);
    sbl = *(const uint4*)(Bl + (size_t)(bn + r2) * K + c2 * 8);

    int st = 0;
    for (int kb = 0; kb < K; kb += 16) {
        {
            unsigned awh[4] = {sah.x, sah.y, sah.z, sah.w};
            unsigned awl[4] = {sal.x, sal.y, sal.z, sal.w};
            unsigned bwh[4] = {sbh.x, sbh.y, sbh.z, sbh.w};
            unsigned bwl[4] = {sbl.x, sbl.y, sbl.z, sbl.w};
#pragma unroll
            for (int p = 0; p < 4; p++) {
                int aaddr = (r2 >> 4) * 128 + ((r2 & 7) * 4 + p) * 4 + ((r2 >> 3) & 1) + 2 * c2;
                As_h[st][aaddr] = awh[p];
                As_l[st][aaddr] = awl[p];
                int baddr = (r2 >> 3) * 64 + ((r2 & 7) * 4 + p) * 2 + c2;
                Bs_h[st][baddr] = bwh[p];
                Bs_l[st][baddr] = bwl[p];
            }
        }
        __syncthreads();

        if (kb + 16 < K) {
            sah = *(const uint4*)(Ah + (size_t)(bm + r2) * K + kb + 16 + c2 * 8);
            sal = *(const uint4*)(Al + (size_t)(bm + r2) * K + kb + 16 + c2 * 8);
            sbh = *(const uint4*)(Bh + (size_t)(bn + r2) * K + kb + 16 + c2 * 8);
            sbl = *(const uint4*)(Bl + (size_t)(bn + r2) * K + kb + 16 + c2 * 8);
        }

        uint4 ah[4], al[4];
        uint2 bh[4], bl[4];
#pragma unroll
        for (int i = 0; i < 4; i++) {
            ah[i] = *(const uint4*)&As_h[st][(wrow * 4 + i) * 128 + lane * 4];
            al[i] = *(const uint4*)&As_l[st][(wrow * 4 + i) * 128 + lane * 4];
        }
#pragma unroll
        for (int j = 0; j < 4; j++) {
            bh[j] = *(const uint2*)&Bs_h[st][(wcol * 4 + j) * 64 + lane * 2];
            bl[j] = *(const uint2*)&Bs_l[st][(wcol * 4 + j) * 64 + lane * 2];
        }
#pragma unroll
        for (int i = 0; i < 4; i++)
#pragma unroll
            for (int j = 0; j < 4; j++) {
                mma_bf16(acc[i][j], ah[i], bl[j]);
                mma_bf16(acc[i][j], al[i], bh[j]);
                mma_bf16(acc[i][j], ah[i], bh[j]);
            }
        st ^= 1;
    }

    const int g = lane >> 2, tig = lane & 3;
#pragma unroll
    for (int i = 0; i < 4; i++) {
#pragma unroll
        for (int j = 0; j < 4; j++) {
            int m0 = bm + wrow * 64 + i * 16 + g;
            int n0 = bn + wcol * 32 + j * 8 + tig * 2;
            float b0 = bias[n0], b1 = bias[n0 + 1];
            float x0 = (acc[i][j].x + b0) * scale, x1 = (acc[i][j].y + b1) * scale;
            float x2 = (acc[i][j].z + b0) * scale, x3 = (acc[i][j].w + b1) * scale;
            if (MODE == 0) {
                size_t i0 = (size_t)m0 * N + n0, i1 = (size_t)(m0 + 8) * N + n0;
                *(float2*)((float*)o0 + i0) = make_float2(x0, x1);
                *(float2*)((float*)o0 + i1) = make_float2(x2, x3);
            } else {
                int b_ = m0 >> 10, hh_ = n0 >> 6, d = n0 & 63;
                if (MODE == 1) {
                    int tt = (m0 >> 7) & 7, mr = m0 & 127;
                    size_t blk = ((size_t)((b_ * 8 + tt) * 16 + hh_)) << 12;
                    int addr = ((d >> 4) * 8 + (mr >> 4)) * 128
                             + ((mr & 7) * 4 + ((d >> 1) & 3)) * 4
                             + ((mr >> 3) & 1) + 2 * ((d >> 3) & 1);
                    unsigned hw, lw;
                    split_pair(x0, x1, hw, lw);
                    ((unsigned*)o0)[blk + addr] = hw; ((unsigned*)o1)[blk + addr] = lw;
                    split_pair(x2, x3, hw, lw);
                    ((unsigned*)o0)[blk + addr + 1] = hw; ((unsigned*)o1)[blk + addr + 1] = lw;
                } else if (MODE == 2) {
                    int stt = (m0 >> 6) & 15, sr = m0 & 63;
                    size_t blk = ((size_t)((b_ * 16 + stt) * 16 + hh_)) << 11;
                    int addr = ((d >> 4) * 8 + (sr >> 3)) * 64
                             + ((sr & 7) * 4 + ((d >> 1) & 3)) * 2 + ((d >> 3) & 1);
                    unsigned hw, lw;
                    split_pair(x0, x1, hw, lw);
                    ((unsigned*)o0)[blk + addr] = hw; ((unsigned*)o1)[blk + addr] = lw;
                    split_pair(x2, x3, hw, lw);
                    ((unsigned*)o0)[blk + addr + 64] = hw; ((unsigned*)o1)[blk + addr + 64] = lw;
                } else {
                    int stt = (m0 >> 6) & 15, sr = m0 & 63;
                    size_t blk = ((size_t)((b_ * 16 + stt) * 16 + hh_)) << 12;
                    int a00 = ((sr >> 3) * 8 + (d >> 3)) * 64
                            + ((d & 7) * 4 + (sr & 3)) * 2 + ((sr >> 2) & 1);
                    unsigned* ov = (unsigned*)o0;
                    ov[blk + a00]           = f2tf32(x0);
                    ov[blk + a00 + 8]       = f2tf32(x1);
                    ov[blk + a00 + 512]     = f2tf32(x2);
                    ov[blk + a00 + 8 + 512] = f2tf32(x3);
                }
            }
        }
    }
}

// ============== flash attention with register-prefetch producer pipeline ==============
#define ZP2 66
#define FLASH4_WORDS (4096+4096+8192+2048+2048+4096+12288+8192+128*ZP2)
#define FLASH4_SMEM (FLASH4_WORDS * 4)

__global__ __launch_bounds__(256)
void flash_mma4(const unsigned* __restrict__ qfh, const unsigned* __restrict__ qfl,
                const unsigned* __restrict__ qrg,
                const unsigned* __restrict__ kfh, const unsigned* __restrict__ kfl,
                const unsigned* __restrict__ vtf, const unsigned* __restrict__ rtf,
                __nv_bfloat16* __restrict__ ctxh, __nv_bfloat16* __restrict__ ctxl)
{
    extern __shared__ unsigned smu[];
    unsigned* qf_h = smu;
    unsigned* qf_l = qf_h + 4096;
    unsigned* qrf  = qf_l + 4096;
    unsigned* kf_h = qrf + 8192;
    unsigned* kf_l = kf_h + 2048;
    unsigned* vf   = kf_l + 2048;
    unsigned* rf   = vf + 4096;        // 3 ring slots x 4096
    unsigned* pfs  = rf + 12288;
    float* Zs      = (float*)(pfs + 8192);

    const int tid = threadIdx.x;
    const int lane = tid & 31;
    const int w = tid >> 5;
    const int g = lane >> 2, tig = lane & 3;
    const int b = blockIdx.y >> 4, hq = blockIdx.y & 15;
    const int bx = blockIdx.x, t0 = bx * 128;
    unsigned* pf = pfs + w * 1024;
    const int m0 = w * 16 + g, m1 = m0 + 8;
    const int T0 = 14 - 2 * bx;

    // ---- q frags: pure contiguous copies ----
    {
        size_t qblk = ((size_t)((b * 8 + bx) * 16 + hq));
        const uint4* qh4 = (const uint4*)(qfh + (qblk << 12));
        const uint4* ql4 = (const uint4*)(qfl + (qblk << 12));
        const uint4* qr4 = (const uint4*)(qrg + (qblk << 13));
#pragma unroll
        for (int x = 0; x < 4; x++) ((uint4*)qf_h)[tid + 256 * x] = qh4[tid + 256 * x];
#pragma unroll
        for (int x = 0; x < 4; x++) ((uint4*)qf_l)[tid + 256 * x] = ql4[tid + 256 * x];
#pragma unroll
        for (int x = 0; x < 8; x++) ((uint4*)qrf)[tid + 256 * x] = qr4[tid + 256 * x];
    }

    // ---- prefetch tile 0 operands into registers ----
    uint4 pk_h[2], pk_l[2], pv[4], pr[4];
    {
        size_t kb_ = (size_t)((b * 16 + 0) * 16 + hq);
        const uint4* kh4 = (const uint4*)(kfh + (kb_ << 11));
        const uint4* kl4 = (const uint4*)(kfl + (kb_ << 11));
        const uint4* v4  = (const uint4*)(vtf + (kb_ << 12));
#pragma unroll
        for (int x = 0; x < 2; x++) { pk_h[x] = kh4[tid + 256 * x]; pk_l[x] = kl4[tid + 256 * x]; }
#pragma unroll
        for (int x = 0; x < 4; x++) pv[x] = v4[tid + 256 * x];
        const uint4* rs = (const uint4*)(rtf + (size_t)(T0 + 2) * 4096);
#pragma unroll
        for (int x = 0; x < 4; x++) pr[x] = rs[tid + 256 * x];
    }

    float m_i[2] = {-1e30f, -1e30f}, l_i[2] = {0.f, 0.f};
    float4 o[8];
#pragma unroll
    for (int j = 0; j < 8; j++) o[j] = make_float4(0.f, 0.f, 0.f, 0.f);

    for (int i = 0; i < 16; i++) {
        const int T = T0 + i;
        __syncthreads();  // prev-tile consumers done; also publishes q frags on iter 0

        // ---- producers: store prefetched regs; iter 0 also fills ring slots T0, T0+1 ----
        {
#pragma unroll
            for (int x = 0; x < 2; x++) {
                ((uint4*)kf_h)[tid + 256 * x] = pk_h[x];
                ((uint4*)kf_l)[tid + 256 * x] = pk_l[x];
            }
#pragma unroll
            for (int x = 0; x < 4; x++) ((uint4*)vf)[tid + 256 * x] = pv[x];
            {
                uint4* rd = (uint4*)(rf + ((T + 2) % 3) * 4096);
#pragma unroll
                for (int x = 0; x < 4; x++) rd[tid + 256 * x] = pr[x];
            }
            if (i == 0) {
#pragma unroll
                for (int it = 0; it < 2; it++) {
                    const uint4* rs = (const uint4*)(rtf + (size_t)(T0 + it) * 4096);
                    uint4* rd = (uint4*)(rf + ((T0 + it) % 3) * 4096);
#pragma unroll
                    for (int x = 0; x < 4; x++) rd[tid + 256 * x] = rs[tid + 256 * x];
                }
            }
        }
        __syncthreads();

        // ---- issue gmem loads for tile i+1 (overlap with compute below) ----
        if (i < 15) {
            size_t kb_ = (size_t)((b * 16 + i + 1) * 16 + hq);
            const uint4* kh4 = (const uint4*)(kfh + (kb_ << 11));
            const uint4* kl4 = (const uint4*)(kfl + (kb_ << 11));
            const uint4* v4  = (const uint4*)(vtf + (kb_ << 12));
#pragma unroll
            for (int x = 0; x < 2; x++) { pk_h[x] = kh4[tid + 256 * x]; pk_l[x] = kl4[tid + 256 * x]; }
#pragma unroll
            for (int x = 0; x < 4; x++) pv[x] = v4[tid + 256 * x];
            const uint4* rs = (const uint4*)(rtf + (size_t)(T + 3) * 4096);
#pragma unroll
            for (int x = 0; x < 4; x++) pr[x] = rs[tid + 256 * x];
        }

        // ---- Z band mma (tf32): n-tiles 14-2w .. 23-2w over 3-slot ring ----
        {
            const unsigned* rslot[3] = { rf + (T % 3) * 4096,
                                         rf + ((T + 1) % 3) * 4096,
                                         rf + ((T + 2) % 3) * 4096 };
            float4 zc[10];
#pragma unroll
            for (int j = 0; j < 10; j++) zc[j] = make_float4(0.f, 0.f, 0.f, 0.f);
#pragma unroll
            for (int ks = 0; ks < 8; ks++) {
                uint4 a = *(const uint4*)(qrf + (ks * 8 + w) * 128 + lane * 4);
#pragma unroll
                for (int j = 0; j < 10; j++) {
                    int nt = 14 - 2 * w + j;
                    uint2 bb = *(const uint2*)(rslot[nt >> 3] + (ks * 8 + (nt & 7)) * 64 + lane * 2);
                    mma_tf32(zc[j], a, bb);
                }
            }
#pragma unroll
            for (int j = 0; j < 10; j++) {
                int u = (14 - 2 * w + j) * 8 + 2 * tig;
                int s = u + m0 - 127;
                if ((unsigned)s < 64u)       Zs[m0 * ZP2 + s]     = zc[j].x;
                if ((unsigned)(s + 1) < 64u) Zs[m0 * ZP2 + s + 1] = zc[j].y;
                int s2 = s + 8;
                if ((unsigned)s2 < 64u)       Zs[m1 * ZP2 + s2]     = zc[j].z;
                if ((unsigned)(s2 + 1) < 64u) Zs[m1 * ZP2 + s2 + 1] = zc[j].w;
            }
        }
        __syncwarp();

        // ---- QK mma (3-term bf16) ----
        float4 sc[8];
#pragma unroll
        for (int j = 0; j < 8; j++) sc[j] = make_float4(0.f, 0.f, 0.f, 0.f);
#pragma unroll
        for (int kb = 0; kb < 4; kb++) {
            uint4 ah = *(const uint4*)(qf_h + (kb * 8 + w) * 128 + lane * 4);
            uint4 al = *(const uint4*)(qf_l + (kb * 8 + w) * 128 + lane * 4);
#pragma unroll
            for (int nt = 0; nt < 8; nt++) {
                uint2 bh = *(const uint2*)(kf_h + (kb * 8 + nt) * 64 + lane * 2);
                uint2 bl = *(const uint2*)(kf_l + (kb * 8 + nt) * 64 + lane * 2);
                mma_bf16(sc[nt], ah, bl);
                mma_bf16(sc[nt], al, bh);
                mma_bf16(sc[nt], ah, bh);
            }
        }

        // ---- diag add + warp-local online softmax ----
        float v0[16], v1[16];
#pragma unroll
        for (int nt = 0; nt < 8; nt++) {
            int s = nt * 8 + 2 * tig;
            v0[2*nt]   = sc[nt].x + Zs[m0 * ZP2 + s];
            v0[2*nt+1] = sc[nt].y + Zs[m0 * ZP2 + s + 1];
            v1[2*nt]   = sc[nt].z + Zs[m1 * ZP2 + s];
            v1[2*nt+1] = sc[nt].w + Zs[m1 * ZP2 + s + 1];
        }
        float lm0 = v0[0], lm1 = v1[0];
#pragma unroll
        for (int e = 1; e < 16; e++) { lm0 = fmaxf(lm0, v0[e]); lm1 = fmaxf(lm1, v1[e]); }
        lm0 = fmaxf(lm0, __shfl_xor_sync(~0u, lm0, 1));
        lm0 = fmaxf(lm0, __shfl_xor_sync(~0u, lm0, 2));
        lm1 = fmaxf(lm1, __shfl_xor_sync(~0u, lm1, 1));
        lm1 = fmaxf(lm1, __shfl_xor_sync(~0u, lm1, 2));
        float mn0 = fmaxf(m_i[0], lm0), mn1 = fmaxf(m_i[1], lm1);
        float al0 = __expf(m_i[0] - mn0), al1 = __expf(m_i[1] - mn1);
        m_i[0] = mn0; m_i[1] = mn1;
        float rs0 = 0.f, rs1 = 0.f;
#pragma unroll
        for (int nt = 0; nt < 8; nt++) {
            int s = nt * 8 + 2 * tig;
            float p00 = __expf(v0[2*nt]   - mn0);
            float p01 = __expf(v0[2*nt+1] - mn0);
            float p10 = __expf(v1[2*nt]   - mn1);
            float p11 = __expf(v1[2*nt+1] - mn1);
            rs0 += p00 + p01; rs1 += p10 + p11;
            int base = nt * 128 + (g * 4 + (s & 3)) * 4 + 2 * ((s >> 2) & 1);
            pf[base]     = f2tf32(p00);
            pf[base + 1] = f2tf32(p10);
            pf[base + 4] = f2tf32(p01);
            pf[base + 5] = f2tf32(p11);
        }
        rs0 += __shfl_xor_sync(~0u, rs0, 1); rs0 += __shfl_xor_sync(~0u, rs0, 2);
        rs1 += __shfl_xor_sync(~0u, rs1, 1); rs1 += __shfl_xor_sync(~0u, rs1, 2);
        l_i[0] = l_i[0] * al0 + rs0;
        l_i[1] = l_i[1] * al1 + rs1;
#pragma unroll
        for (int j = 0; j < 8; j++) {
            o[j].x *= al0; o[j].y *= al0; o[j].z *= al1; o[j].w *= al1;
        }
        __syncwarp();

        // ---- PV mma (tf32): O += P @ V ----
#pragma unroll
        for (int ks = 0; ks < 8; ks++) {
            uint4 a = *(const uint4*)(pf + ks * 128 + lane * 4);
#pragma unroll
            for (int nt = 0; nt < 8; nt++) {
                uint2 bb = *(const uint2*)(vf + (ks * 8 + nt) * 64 + lane * 2);
                mma_tf32(o[nt], a, bb);
            }
        }
    }

    // ---- epilogue: normalize, split to bf16 hi/lo (row-major) ----
    float inv0 = 1.f / l_i[0], inv1 = 1.f / l_i[1];
#pragma unroll
    for (int nt = 0; nt < 8; nt++) {
        int d = nt * 8 + 2 * tig;
        size_t i0 = (size_t)(b * TT + t0 + m0) * CC + hq * HD + d;
        size_t i1 = (size_t)(b * TT + t0 + m1) * CC + hq * HD + d;
        unsigned hh, ll;
        split_pair(o[nt].x * inv0, o[nt].y * inv0, hh, ll);
        ((unsigned*)ctxh)[i0 >> 1] = hh; ((unsigned*)ctxl)[i0 >> 1] = ll;
        split_pair(o[nt].z * inv1, o[nt].w * inv1, hh, ll);
        ((unsigned*)ctxh)[i1 >> 1] = hh; ((unsigned*)ctxl)[i1 >> 1] = ll;
    }
}

// ------------------------------ launch ------------------------------
extern "C" void kernel_launch(void* const* d_in, const int* in_sizes, int n_in,
                              void* d_out, int out_size)
{
    const float* query   = (const float*)d_in[0];
    const float* key     = (const float*)d_in[1];
    const float* value   = (const float*)d_in[2];
    const float* Wq      = (const float*)d_in[3];
    const float* bq      = (const float*)d_in[4];
    const float* Wk      = (const float*)d_in[5];
    const float* bk      = (const float*)d_in[6];
    const float* Wv      = (const float*)d_in[7];
    const float* bv      = (const float*)d_in[8];
    const float* Wo      = (const float*)d_in[9];
    const float* bo      = (const float*)d_in[10];
    const float* rel_emb = (const float*)d_in[11];
    float* out = (float*)d_out;

    __nv_bfloat16 *inh, *inl, *Wh, *Wl, *ctxh, *ctxl;
    unsigned *qfh, *qfl, *kfh, *kfl, *vtf, *qrf, *rtf;
    cudaGetSymbolAddress((void**)&inh, g_inh);
    cudaGetSymbolAddress((void**)&inl, g_inl);
    cudaGetSymbolAddress((void**)&Wh, g_Wh);
    cudaGetSymbolAddress((void**)&Wl, g_Wl);
    cudaGetSymbolAddress((void**)&qfh, g_qfh);
    cudaGetSymbolAddress((void**)&qfl, g_qfl);
    cudaGetSymbolAddress((void**)&kfh, g_kfh);
    cudaGetSymbolAddress((void**)&kfl, g_kfl);
    cudaGetSymbolAddress((void**)&vtf, g_vtf);
    cudaGetSymbolAddress((void**)&qrf, g_qrf);
    cudaGetSymbolAddress((void**)&rtf, g_rtf);
    cudaGetSymbolAddress((void**)&ctxh, g_ctxh);
    cudaGetSymbolAddress((void**)&ctxl, g_ctxl);

    convA<<<12288, 256>>>(query, key, value, inh, inl, qrf);
    convW<<<4608, 256>>>(Wq, Wk, Wv, Wo, rel_emb, Wh, Wl, rtf);

    dim3 gproj(CC / 128, (BB * TT) / 128);
    gemm2<1><<<gproj, 256>>>(inh + 0*(size_t)NEL, inl + 0*(size_t)NEL,
        Wh + 0*(size_t)NW, Wl + 0*(size_t)NW, bq, qfh, qfl, BB*TT, CC, CC, 8.0f);
    gemm2<2><<<gproj, 256>>>(inh + 1*(size_t)NEL, inl + 1*(size_t)NEL,
        Wh + 1*(size_t)NW, Wl + 1*(size_t)NW, bk, kfh, kfl, BB*TT, CC, CC, 1.0f);
    gemm2<3><<<gproj, 256>>>(inh + 2*(size_t)NEL, inl + 2*(size_t)NEL,
        Wh + 2*(size_t)NW, Wl + 2*(size_t)NW, bv, vtf, nullptr, BB*TT, CC, CC, 1.0f);

    cudaFuncSetAttribute(flash_mma4, cudaFuncAttributeMaxDynamicSharedMemorySize, FLASH4_SMEM);
    flash_mma4<<<dim3(TT / 128, BB * HH), 256, FLASH4_SMEM>>>(
        qfh, qfl, qrf, kfh, kfl, vtf, rtf, ctxh, ctxl);

    gemm2<0><<<gproj, 256>>>(ctxh, ctxl, Wh + 3*(size_t)NW, Wl + 3*(size_t)NW,
        bo, out, nullptr, BB*TT, CC, CC, 1.0f);
}

// round 11
// speedup vs baseline: 1.0552x; 1.0552x over previous
#include <cuda_runtime.h>
#include <cuda_bf16.h>
#include <stdint.h>
#include <math.h>

#define BB 4
#define TT 1024
#define CC 1024
#define HH 16
#define HD 64
#define NEL (BB*TT*CC)          // 4194304
#define NW  (CC*CC)             // 1048576

// ---------------- scratch (device globals: allocation-free) ----------------
__device__ __nv_bfloat16 g_inh[3][NEL], g_inl[3][NEL];   // split query,key,value (row-major)
__device__ __nv_bfloat16 g_Wh[4][NW],  g_Wl[4][NW];      // split Wq,Wk,Wv,Wo (row-major)
__device__ unsigned g_qfh[NEL/2], g_qfl[NEL/2];          // proj q (x8) bf16 A-frags
__device__ unsigned g_kfh[NEL/2], g_kfl[NEL/2];          // proj k bf16 B-frags
__device__ unsigned g_vtf[NEL];                          // proj v tf32 B-frags
__device__ unsigned g_qrf[NEL];                          // raw q x8 tf32 A-frags
__device__ unsigned g_rtf[32*4096];                      // relpad tf32 B-frag tiles
__device__ __nv_bfloat16 g_ctxh[NEL], g_ctxl[NEL];       // attention out, split row-major

// ---------------- helpers ----------------
__device__ __forceinline__ unsigned f2tf32(float x) {
    unsigned u;
    asm("cvt.rna.tf32.f32 %0, %1;" : "=r"(u) : "f"(x));
    return u;
}
__device__ __forceinline__ void mma_tf32(float4& c, const uint4& a, const uint2& b) {
    asm volatile(
        "mma.sync.aligned.m16n8k8.row.col.f32.tf32.tf32.f32 "
        "{%0,%1,%2,%3}, {%4,%5,%6,%7}, {%8,%9}, {%0,%1,%2,%3};"
        : "+f"(c.x), "+f"(c.y), "+f"(c.z), "+f"(c.w)
        : "r"(a.x), "r"(a.y), "r"(a.z), "r"(a.w), "r"(b.x), "r"(b.y));
}
__device__ __forceinline__ void mma_bf16(float4& c, const uint4& a, const uint2& b) {
    asm volatile(
        "mma.sync.aligned.m16n8k16.row.col.f32.bf16.bf16.f32 "
        "{%0,%1,%2,%3}, {%4,%5,%6,%7}, {%8,%9}, {%0,%1,%2,%3};"
        : "+f"(c.x), "+f"(c.y), "+f"(c.z), "+f"(c.w)
        : "r"(a.x), "r"(a.y), "r"(a.z), "r"(a.w), "r"(b.x), "r"(b.y));
}
__device__ __forceinline__ void split_pair(float x, float y, unsigned& hi, unsigned& lo) {
    __nv_bfloat16 hx = __float2bfloat16(x), hy = __float2bfloat16(y);
    __nv_bfloat162 H; H.x = hx; H.y = hy;
    __nv_bfloat162 L;
    L.x = __float2bfloat16(x - __bfloat162float(hx));
    L.y = __float2bfloat16(y - __bfloat162float(hy));
    hi = *reinterpret_cast<unsigned*>(&H);
    lo = *reinterpret_cast<unsigned*>(&L);
}

// ---------------- fused one-time converts ----------------
// blocks [0, 12288): split q/k/v row-major + qraw tf32 A-frags
// blocks [12288, 16384): split 4 weight matrices
// blocks [16384, 16896): relpad tf32 B-frag tiles
__global__ void convAll(const float* __restrict__ q, const float* __restrict__ k,
                        const float* __restrict__ v,
                        const float* __restrict__ Wq, const float* __restrict__ Wk,
                        const float* __restrict__ Wv, const float* __restrict__ Wo,
                        const float* __restrict__ rel_emb,
                        __nv_bfloat16* __restrict__ inh, __nv_bfloat16* __restrict__ inl,
                        unsigned* __restrict__ qrf,
                        __nv_bfloat16* __restrict__ Wh, __nv_bfloat16* __restrict__ Wl,
                        unsigned* __restrict__ rtf)
{
    int blk = blockIdx.x;
    if (blk < 12288) {
        int arr = blk >> 12;
        int i = ((blk & 4095) << 8) + threadIdx.x;
        const float* src = arr == 0 ? q : (arr == 1 ? k : v);
        float4 v4 = ((const float4*)src)[i];
        unsigned h0, l0, h1, l1;
        split_pair(v4.x, v4.y, h0, l0);
        split_pair(v4.z, v4.w, h1, l1);
        ((uint2*)(inh + (size_t)arr * NEL))[i] = make_uint2(h0, h1);
        ((uint2*)(inl + (size_t)arr * NEL))[i] = make_uint2(l0, l1);
        if (arr == 0) {
            int e = i * 4;
            int m = e >> 10, ch = e & 1023;
            int hh_ = ch >> 6, d = ch & 63;
            int b_ = m >> 10, tt = (m >> 7) & 7, mr = m & 127;
            size_t blko = ((size_t)((b_ * 8 + tt) * 16 + hh_)) << 13;
            int base = ((d >> 3) * 8 + (mr >> 4)) * 128 + (mr & 7) * 16
                     + ((mr >> 3) & 1) + 2 * ((d >> 2) & 1);
            qrf[blko + base +  0] = f2tf32(8.f * v4.x);
            qrf[blko + base +  4] = f2tf32(8.f * v4.y);
            qrf[blko + base +  8] = f2tf32(8.f * v4.z);
            qrf[blko + base + 12] = f2tf32(8.f * v4.w);
        }
    } else if (blk < 16384) {
        int wblk = blk - 12288;
        int arr = wblk >> 10;
        int i = ((wblk & 1023) << 8) + threadIdx.x;
        const float* src = arr == 0 ? Wq : (arr == 1 ? Wk : (arr == 2 ? Wv : Wo));
        float4 v4 = ((const float4*)src)[i];
        unsigned h0, l0, h1, l1;
        split_pair(v4.x, v4.y, h0, l0);
        split_pair(v4.z, v4.w, h1, l1);
        ((uint2*)(Wh + (size_t)arr * NW))[i] = make_uint2(h0, h1);
        ((uint2*)(Wl + (size_t)arr * NW))[i] = make_uint2(l0, l1);
    } else {
        int e = ((blk - 16384) << 8) + threadIdx.x;
        int tt = e >> 12, rem = e & 4095;
        int ul = rem >> 6, d = rem & 63;
        int u = tt * 64 + ul;
        int src = u - 24;
        src = src < 0 ? 0 : (src > 1998 ? 1998 : src);
        int addr = tt * 4096 + ((d >> 3) * 8 + (ul >> 3)) * 64
                 + ((ul & 7) * 4 + (d & 3)) * 2 + ((d >> 2) & 1);
        rtf[addr] = f2tf32(rel_emb[src * HD + d]);
    }
}

// ========== fused Q/K/V projection GEMM (single launch, blockIdx.z = mode) ==========
// Mainloop identical to round-6 gemm2 (bit-identical arithmetic). Epilogue:
// z=0: Q -> bf16 A-frags hi/lo (scale 8); z=1: K -> bf16 B-frags hi/lo; z=2: V -> tf32 B-frags.
__global__ __launch_bounds__(256)
void gemm_qkv(const __nv_bfloat16* __restrict__ inh, const __nv_bfloat16* __restrict__ inl,
              const __nv_bfloat16* __restrict__ Whp, const __nv_bfloat16* __restrict__ Wlp,
              const float* __restrict__ bq, const float* __restrict__ bk,
              const float* __restrict__ bv,
              unsigned* __restrict__ qfh, unsigned* __restrict__ qfl,
              unsigned* __restrict__ kfh, unsigned* __restrict__ kfl,
              unsigned* __restrict__ vtf)
{
    __shared__ unsigned As_h[2][1024], As_l[2][1024];
    __shared__ unsigned Bs_h[2][1024], Bs_l[2][1024];

    const int tid = threadIdx.x;
    const int lane = tid & 31;
    const int warp = tid >> 5;
    const int wrow = warp & 1, wcol = warp >> 1;
    const int bm = blockIdx.y * 128, bn = blockIdx.x * 128;
    const int z = blockIdx.z;                      // 0=Q, 1=K, 2=V
    const int r2 = tid >> 1, c2 = tid & 1;
    const int K = CC, N = CC;

    const __nv_bfloat16* Ah = inh + (size_t)z * NEL;
    const __nv_bfloat16* Al = inl + (size_t)z * NEL;
    const __nv_bfloat16* Bh = Whp + (size_t)z * NW;
    const __nv_bfloat16* Bl = Wlp + (size_t)z * NW;
    const float* bias = z == 0 ? bq : (z == 1 ? bk : bv);
    const float scale = z == 0 ? 8.0f : 1.0f;

    float4 acc[4][4];
#pragma unroll
    for (int i = 0; i < 4; i++)
#pragma unroll
        for (int j = 0; j < 4; j++) acc[i][j] = make_float4(0.f, 0.f, 0.f, 0.f);

    uint4 sah, sal, sbh, sbl;
    sah = *(const uint4*)(Ah + (size_t)(bm + r2) * K + c2 * 8);
    sal = *(const uint4*)(Al + (size_t)(bm + r2) * K + c2 * 8);
    sbh = *(const uint4*)(Bh + (size_t)(bn + r2) * K + c2 * 8);
    sbl = *(const uint4*)(Bl + (size_t)(bn + r2) * K + c2 * 8);

    int st = 0;
    for (int kb = 0; kb < K; kb += 16) {
        {
            unsigned awh[4] = {sah.x, sah.y, sah.z, sah.w};
            unsigned awl[4] = {sal.x, sal.y, sal.z, sal.w};
            unsigned bwh[4] = {sbh.x, sbh.y, sbh.z, sbh.w};
            unsigned bwl[4] = {sbl.x, sbl.y, sbl.z, sbl.w};
#pragma unroll
            for (int p = 0; p < 4; p++) {
                int aaddr = (r2 >> 4) * 128 + ((r2 & 7) * 4 + p) * 4 + ((r2 >> 3) & 1) + 2 * c2;
                As_h[st][aaddr] = awh[p];
                As_l[st][aaddr] = awl[p];
                int baddr = (r2 >> 3) * 64 + ((r2 & 7) * 4 + p) * 2 + c2;
                Bs_h[st][baddr] = bwh[p];
                Bs_l[st][baddr] = bwl[p];
            }
        }
        __syncthreads();

        if (kb + 16 < K) {
            sah = *(const uint4*)(Ah + (size_t)(bm + r2) * K + kb + 16 + c2 * 8);
            sal = *(const uint4*)(Al + (size_t)(bm + r2) * K + kb + 16 + c2 * 8);
            sbh = *(const uint4*)(Bh + (size_t)(bn + r2) * K + kb + 16 + c2 * 8);
            sbl = *(const uint4*)(Bl + (size_t)(bn + r2) * K + kb + 16 + c2 * 8);
        }

        uint4 ah[4], al[4];
        uint2 bh[4], bl[4];
#pragma unroll
        for (int i = 0; i < 4; i++) {
            ah[i] = *(const uint4*)&As_h[st][(wrow * 4 + i) * 128 + lane * 4];
            al[i] = *(const uint4*)&As_l[st][(wrow * 4 + i) * 128 + lane * 4];
        }
#pragma unroll
        for (int j = 0; j < 4; j++) {
            bh[j] = *(const uint2*)&Bs_h[st][(wcol * 4 + j) * 64 + lane * 2];
            bl[j] = *(const uint2*)&Bs_l[st][(wcol * 4 + j) * 64 + lane * 2];
        }
#pragma unroll
        for (int i = 0; i < 4; i++)
#pragma unroll
            for (int j = 0; j < 4; j++) {
                mma_bf16(acc[i][j], ah[i], bl[j]);
                mma_bf16(acc[i][j], al[i], bh[j]);
                mma_bf16(acc[i][j], ah[i], bh[j]);
            }
        st ^= 1;
    }

    const int g = lane >> 2, tig = lane & 3;
#pragma unroll
    for (int i = 0; i < 4; i++) {
#pragma unroll
        for (int j = 0; j < 4; j++) {
            int m0 = bm + wrow * 64 + i * 16 + g;
            int n0 = bn + wcol * 32 + j * 8 + tig * 2;
            float b0 = bias[n0], b1 = bias[n0 + 1];
            float x0 = (acc[i][j].x + b0) * scale, x1 = (acc[i][j].y + b1) * scale;
            float x2 = (acc[i][j].z + b0) * scale, x3 = (acc[i][j].w + b1) * scale;
            int b_ = m0 >> 10, hh_ = n0 >> 6, d = n0 & 63;
            if (z == 0) {
                int tt = (m0 >> 7) & 7, mr = m0 & 127;
                size_t blk = ((size_t)((b_ * 8 + tt) * 16 + hh_)) << 12;
                int addr = ((d >> 4) * 8 + (mr >> 4)) * 128
                         + ((mr & 7) * 4 + ((d >> 1) & 3)) * 4
                         + ((mr >> 3) & 1) + 2 * ((d >> 3) & 1);
                unsigned hw, lw;
                split_pair(x0, x1, hw, lw);
                qfh[blk + addr] = hw; qfl[blk + addr] = lw;
                split_pair(x2, x3, hw, lw);
                qfh[blk + addr + 1] = hw; qfl[blk + addr + 1] = lw;
            } else if (z == 1) {
                int stt = (m0 >> 6) & 15, sr = m0 & 63;
                size_t blk = ((size_t)((b_ * 16 + stt) * 16 + hh_)) << 11;
                int addr = ((d >> 4) * 8 + (sr >> 3)) * 64
                         + ((sr & 7) * 4 + ((d >> 1) & 3)) * 2 + ((d >> 3) & 1);
                unsigned hw, lw;
                split_pair(x0, x1, hw, lw);
                kfh[blk + addr] = hw; kfl[blk + addr] = lw;
                split_pair(x2, x3, hw, lw);
                kfh[blk + addr + 64] = hw; kfl[blk + addr + 64] = lw;
            } else {
                int stt = (m0 >> 6) & 15, sr = m0 & 63;
                size_t blk = ((size_t)((b_ * 16 + stt) * 16 + hh_)) << 12;
                int a00 = ((sr >> 3) * 8 + (d >> 3)) * 64
                        + ((d & 7) * 4 + (sr & 3)) * 2 + ((sr >> 2) & 1);
                vtf[blk + a00]           = f2tf32(x0);
                vtf[blk + a00 + 8]       = f2tf32(x1);
                vtf[blk + a00 + 512]     = f2tf32(x2);
                vtf[blk + a00 + 8 + 512] = f2tf32(x3);
            }
        }
    }
}

// ========== bf16 3-term NT GEMM, fp32 row-major out (Wo projection) ==========
__global__ __launch_bounds__(256)
void gemm_out(const __nv_bfloat16* __restrict__ Ah, const __nv_bfloat16* __restrict__ Al,
              const __nv_bfloat16* __restrict__ Bh, const __nv_bfloat16* __restrict__ Bl,
              const float* __restrict__ bias, float* __restrict__ o0, int N, int K)
{
    __shared__ unsigned As_h[2][1024], As_l[2][1024];
    __shared__ unsigned Bs_h[2][1024], Bs_l[2][1024];

    const int tid = threadIdx.x;
    const int lane = tid & 31;
    const int warp = tid >> 5;
    const int wrow = warp & 1, wcol = warp >> 1;
    const int bm = blockIdx.y * 128, bn = blockIdx.x * 128;
    const int r2 = tid >> 1, c2 = tid & 1;

    float4 acc[4][4];
#pragma unroll
    for (int i = 0; i < 4; i++)
#pragma unroll
        for (int j = 0; j < 4; j++) acc[i][j] = make_float4(0.f, 0.f, 0.f, 0.f);

    uint4 sah, sal, sbh, sbl;
    sah = *(const uint4*)(Ah + (size_t)(bm + r2) * K + c2 * 8);
    sal = *(const uint4*)(Al + (size_t)(bm + r2) * K + c2 * 8);
    sbh = *(const uint4*)(Bh + (size_t)(bn + r2) * K + c2 * 8);
    sbl = *(const uint4*)(Bl + (size_t)(bn + r2) * K + c2 * 8);

    int st = 0;
    for (int kb = 0; kb < K; kb += 16) {
        {
            unsigned awh[4] = {sah.x, sah.y, sah.z, sah.w};
            unsigned awl[4] = {sal.x, sal.y, sal.z, sal.w};
            unsigned bwh[4] = {sbh.x, sbh.y, sbh.z, sbh.w};
            unsigned bwl[4] = {sbl.x, sbl.y, sbl.z, sbl.w};
#pragma unroll
            for (int p = 0; p < 4; p++) {
                int aaddr = (r2 >> 4) * 128 + ((r2 & 7) * 4 + p) * 4 + ((r2 >> 3) & 1) + 2 * c2;
                As_h[st][aaddr] = awh[p];
                As_l[st][aaddr] = awl[p];
                int baddr = (r2 >> 3) * 64 + ((r2 & 7) * 4 + p) * 2 + c2;
                Bs_h[st][baddr] = bwh[p];
                Bs_l[st][baddr] = bwl[p];
            }
        }
        __syncthreads();

        if (kb + 16 < K) {
            sah = *(const uint4*)(Ah + (size_t)(bm + r2) * K + kb + 16 + c2 * 8);
            sal = *(const uint4*)(Al + (size_t)(bm + r2) * K + kb + 16 + c2 * 8);
            sbh = *(const uint4*)(Bh + (size_t)(bn + r2) * K + kb + 16 + c2 * 8);
            sbl = *(const uint4*)(Bl + (size_t)(bn + r2) * K + kb + 16 + c2 * 8);
        }

        uint4 ah[4], al[4];
        uint2 bh[4], bl[4];
#pragma unroll
        for (int i = 0; i < 4; i++) {
            ah[i] = *(const uint4*)&As_h[st][(wrow * 4 + i) * 128 + lane * 4];
            al[i] = *(const uint4*)&As_l[st][(wrow * 4 + i) * 128 + lane * 4];
        }
#pragma unroll
        for (int j = 0; j < 4; j++) {
            bh[j] = *(const uint2*)&Bs_h[st][(wcol * 4 + j) * 64 + lane * 2];
            bl[j] = *(const uint2*)&Bs_l[st][(wcol * 4 + j) * 64 + lane * 2];
        }
#pragma unroll
        for (int i = 0; i < 4; i++)
#pragma unroll
            for (int j = 0; j < 4; j++) {
                mma_bf16(acc[i][j], ah[i], bl[j]);
                mma_bf16(acc[i][j], al[i], bh[j]);
                mma_bf16(acc[i][j], ah[i], bh[j]);
            }
        st ^= 1;
    }

    const int g = lane >> 2, tig = lane & 3;
#pragma unroll
    for (int i = 0; i < 4; i++) {
#pragma unroll
        for (int j = 0; j < 4; j++) {
            int m0 = bm + wrow * 64 + i * 16 + g;
            int n0 = bn + wcol * 32 + j * 8 + tig * 2;
            float b0 = bias[n0], b1 = bias[n0 + 1];
            size_t i0 = (size_t)m0 * N + n0, i1 = (size_t)(m0 + 8) * N + n0;
            *(float2*)(o0 + i0) = make_float2(acc[i][j].x + b0, acc[i][j].y + b1);
            *(float2*)(o0 + i1) = make_float2(acc[i][j].z + b0, acc[i][j].w + b1);
        }
    }
}

// ============== flash attention (round-6 config — best measured) ==============
#define ZP2 66
#define FLASH3_WORDS (4096+4096+8192+2048+2048+4096+12288+8192+128*ZP2)
#define FLASH3_SMEM (FLASH3_WORDS * 4)

__global__ __launch_bounds__(256)
void flash_mma3(const unsigned* __restrict__ qfh, const unsigned* __restrict__ qfl,
                const unsigned* __restrict__ qrg,
                const unsigned* __restrict__ kfh, const unsigned* __restrict__ kfl,
                const unsigned* __restrict__ vtf, const unsigned* __restrict__ rtf,
                __nv_bfloat16* __restrict__ ctxh, __nv_bfloat16* __restrict__ ctxl)
{
    extern __shared__ unsigned smu[];
    unsigned* qf_h = smu;
    unsigned* qf_l = qf_h + 4096;
    unsigned* qrf  = qf_l + 4096;
    unsigned* kf_h = qrf + 8192;
    unsigned* kf_l = kf_h + 2048;
    unsigned* vf   = kf_l + 2048;
    unsigned* rf   = vf + 4096;
    unsigned* pfs  = rf + 12288;
    float* Zs      = (float*)(pfs + 8192);

    const int tid = threadIdx.x;
    const int lane = tid & 31;
    const int w = tid >> 5;
    const int g = lane >> 2, tig = lane & 3;
    const int b = blockIdx.y >> 4, hq = blockIdx.y & 15;
    const int bx = blockIdx.x, t0 = bx * 128;
    unsigned* pf = pfs + w * 1024;
    const int m0 = w * 16 + g, m1 = m0 + 8;

    {
        size_t qblk = ((size_t)((b * 8 + bx) * 16 + hq));
        const uint4* qh4 = (const uint4*)(qfh + (qblk << 12));
        const uint4* ql4 = (const uint4*)(qfl + (qblk << 12));
        const uint4* qr4 = (const uint4*)(qrg + (qblk << 13));
#pragma unroll
        for (int x = 0; x < 4; x++) ((uint4*)qf_h)[tid + 256 * x] = qh4[tid + 256 * x];
#pragma unroll
        for (int x = 0; x < 4; x++) ((uint4*)qf_l)[tid + 256 * x] = ql4[tid + 256 * x];
#pragma unroll
        for (int x = 0; x < 8; x++) ((uint4*)qrf)[tid + 256 * x] = qr4[tid + 256 * x];
    }

    float m_i[2] = {-1e30f, -1e30f}, l_i[2] = {0.f, 0.f};
    float4 o[8];
#pragma unroll
    for (int j = 0; j < 8; j++) o[j] = make_float4(0.f, 0.f, 0.f, 0.f);

    for (int i = 0; i < 16; i++) {
        int T = i - 2 * bx + 14;
        __syncthreads();

        {
            size_t kb_ = (size_t)((b * 16 + i) * 16 + hq);
            const uint4* kh4 = (const uint4*)(kfh + (kb_ << 11));
            const uint4* kl4 = (const uint4*)(kfl + (kb_ << 11));
            const uint4* v4  = (const uint4*)(vtf + (kb_ << 12));
#pragma unroll
            for (int x = 0; x < 2; x++) ((uint4*)kf_h)[tid + 256 * x] = kh4[tid + 256 * x];
#pragma unroll
            for (int x = 0; x < 2; x++) ((uint4*)kf_l)[tid + 256 * x] = kl4[tid + 256 * x];
#pragma unroll
            for (int x = 0; x < 4; x++) ((uint4*)vf)[tid + 256 * x] = v4[tid + 256 * x];
            if (i == 0) {
#pragma unroll
                for (int it = 0; it < 2; it++) {
                    const uint4* rs = (const uint4*)(rtf + (size_t)(T + it) * 4096);
                    uint4* rd = (uint4*)(rf + ((T + it) % 3) * 4096);
#pragma unroll
                    for (int x = 0; x < 4; x++) rd[tid + 256 * x] = rs[tid + 256 * x];
                }
            }
            {
                const uint4* rs = (const uint4*)(rtf + (size_t)(T + 2) * 4096);
                uint4* rd = (uint4*)(rf + ((T + 2) % 3) * 4096);
#pragma unroll
                for (int x = 0; x < 4; x++) rd[tid + 256 * x] = rs[tid + 256 * x];
            }
        }
        __syncthreads();

        {
            const unsigned* rslot[3] = { rf + (T % 3) * 4096,
                                         rf + ((T + 1) % 3) * 4096,
                                         rf + ((T + 2) % 3) * 4096 };
            float4 zc[10];
#pragma unroll
            for (int j = 0; j < 10; j++) zc[j] = make_float4(0.f, 0.f, 0.f, 0.f);
#pragma unroll
            for (int ks = 0; ks < 8; ks++) {
                uint4 a = *(const uint4*)(qrf + (ks * 8 + w) * 128 + lane * 4);
#pragma unroll
                for (int j = 0; j < 10; j++) {
                    int nt = 14 - 2 * w + j;
                    uint2 bb = *(const uint2*)(rslot[nt >> 3] + (ks * 8 + (nt & 7)) * 64 + lane * 2);
                    mma_tf32(zc[j], a, bb);
                }
            }
#pragma unroll
            for (int j = 0; j < 10; j++) {
                int u = (14 - 2 * w + j) * 8 + 2 * tig;
                int s = u + m0 - 127;
                if ((unsigned)s < 64u)       Zs[m0 * ZP2 + s]     = zc[j].x;
                if ((unsigned)(s + 1) < 64u) Zs[m0 * ZP2 + s + 1] = zc[j].y;
                int s2 = s + 8;
                if ((unsigned)s2 < 64u)       Zs[m1 * ZP2 + s2]     = zc[j].z;
                if ((unsigned)(s2 + 1) < 64u) Zs[m1 * ZP2 + s2 + 1] = zc[j].w;
            }
        }
        __syncwarp();

        float4 sc[8];
#pragma unroll
        for (int j = 0; j < 8; j++) sc[j] = make_float4(0.f, 0.f, 0.f, 0.f);
#pragma unroll
        for (int kb = 0; kb < 4; kb++) {
            uint4 ah = *(const uint4*)(qf_h + (kb * 8 + w) * 128 + lane * 4);
            uint4 al = *(const uint4*)(qf_l + (kb * 8 + w) * 128 + lane * 4);
#pragma unroll
            for (int nt = 0; nt < 8; nt++) {
                uint2 bh = *(const uint2*)(kf_h + (kb * 8 + nt) * 64 + lane * 2);
                uint2 bl = *(const uint2*)(kf_l + (kb * 8 + nt) * 64 + lane * 2);
                mma_bf16(sc[nt], ah, bl);
                mma_bf16(sc[nt], al, bh);
                mma_bf16(sc[nt], ah, bh);
            }
        }

        float v0[16], v1[16];
#pragma unroll
        for (int nt = 0; nt < 8; nt++) {
            int s = nt * 8 + 2 * tig;
            v0[2*nt]   = sc[nt].x + Zs[m0 * ZP2 + s];
            v0[2*nt+1] = sc[nt].y + Zs[m0 * ZP2 + s + 1];
            v1[2*nt]   = sc[nt].z + Zs[m1 * ZP2 + s];
            v1[2*nt+1] = sc[nt].w + Zs[m1 * ZP2 + s + 1];
        }
        float lm0 = v0[0], lm1 = v1[0];
#pragma unroll
        for (int e = 1; e < 16; e++) { lm0 = fmaxf(lm0, v0[e]); lm1 = fmaxf(lm1, v1[e]); }
        lm0 = fmaxf(lm0, __shfl_xor_sync(~0u, lm0, 1));
        lm0 = fmaxf(lm0, __shfl_xor_sync(~0u, lm0, 2));
        lm1 = fmaxf(lm1, __shfl_xor_sync(~0u, lm1, 1));
        lm1 = fmaxf(lm1, __shfl_xor_sync(~0u, lm1, 2));
        float mn0 = fmaxf(m_i[0], lm0), mn1 = fmaxf(m_i[1], lm1);
        float al0 = __expf(m_i[0] - mn0), al1 = __expf(m_i[1] - mn1);
        m_i[0] = mn0; m_i[1] = mn1;
        float rs0 = 0.f, rs1 = 0.f;
#pragma unroll
        for (int nt = 0; nt < 8; nt++) {
            int s = nt * 8 + 2 * tig;
            float p00 = __expf(v0[2*nt]   - mn0);
            float p01 = __expf(v0[2*nt+1] - mn0);
            float p10 = __expf(v1[2*nt]   - mn1);
            float p11 = __expf(v1[2*nt+1] - mn1);
            rs0 += p00 + p01; rs1 += p10 + p11;
            int base = nt * 128 + (g * 4 + (s & 3)) * 4 + 2 * ((s >> 2) & 1);
            pf[base]     = f2tf32(p00);
            pf[base + 1] = f2tf32(p10);
            pf[base + 4] = f2tf32(p01);
            pf[base + 5] = f2tf32(p11);
        }
        rs0 += __shfl_xor_sync(~0u, rs0, 1); rs0 += __shfl_xor_sync(~0u, rs0, 2);
        rs1 += __shfl_xor_sync(~0u, rs1, 1); rs1 += __shfl_xor_sync(~0u, rs1, 2);
        l_i[0] = l_i[0] * al0 + rs0;
        l_i[1] = l_i[1] * al1 + rs1;
#pragma unroll
        for (int j = 0; j < 8; j++) {
            o[j].x *= al0; o[j].y *= al0; o[j].z *= al1; o[j].w *= al1;
        }
        __syncwarp();

#pragma unroll
        for (int ks = 0; ks < 8; ks++) {
            uint4 a = *(const uint4*)(pf + ks * 128 + lane * 4);
#pragma unroll
            for (int nt = 0; nt < 8; nt++) {
                uint2 bb = *(const uint2*)(vf + (ks * 8 + nt) * 64 + lane * 2);
                mma_tf32(o[nt], a, bb);
            }
        }
    }

    float inv0 = 1.f / l_i[0], inv1 = 1.f / l_i[1];
#pragma unroll
    for (int nt = 0; nt < 8; nt++) {
        int d = nt * 8 + 2 * tig;
        size_t i0 = (size_t)(b * TT + t0 + m0) * CC + hq * HD + d;
        size_t i1 = (size_t)(b * TT + t0 + m1) * CC + hq * HD + d;
        unsigned hh, ll;
        split_pair(o[nt].x * inv0, o[nt].y * inv0, hh, ll);
        ((unsigned*)ctxh)[i0 >> 1] = hh; ((unsigned*)ctxl)[i0 >> 1] = ll;
        split_pair(o[nt].z * inv1, o[nt].w * inv1, hh, ll);
        ((unsigned*)ctxh)[i1 >> 1] = hh; ((unsigned*)ctxl)[i1 >> 1] = ll;
    }
}

// ------------------------------ launch ------------------------------
extern "C" void kernel_launch(void* const* d_in, const int* in_sizes, int n_in,
                              void* d_out, int out_size)
{
    const float* query   = (const float*)d_in[0];
    const float* key     = (const float*)d_in[1];
    const float* value   = (const float*)d_in[2];
    const float* Wq      = (const float*)d_in[3];
    const float* bq      = (const float*)d_in[4];
    const float* Wk      = (const float*)d_in[5];
    const float* bk      = (const float*)d_in[6];
    const float* Wv      = (const float*)d_in[7];
    const float* bv      = (const float*)d_in[8];
    const float* Wo      = (const float*)d_in[9];
    const float* bo      = (const float*)d_in[10];
    const float* rel_emb = (const float*)d_in[11];
    float* out = (float*)d_out;

    __nv_bfloat16 *inh, *inl, *Wh, *Wl, *ctxh, *ctxl;
    unsigned *qfh, *qfl, *kfh, *kfl, *vtf, *qrf, *rtf;
    cudaGetSymbolAddress((void**)&inh, g_inh);
    cudaGetSymbolAddress((void**)&inl, g_inl);
    cudaGetSymbolAddress((void**)&Wh, g_Wh);
    cudaGetSymbolAddress((void**)&Wl, g_Wl);
    cudaGetSymbolAddress((void**)&qfh, g_qfh);
    cudaGetSymbolAddress((void**)&qfl, g_qfl);
    cudaGetSymbolAddress((void**)&kfh, g_kfh);
    cudaGetSymbolAddress((void**)&kfl, g_kfl);
    cudaGetSymbolAddress((void**)&vtf, g_vtf);
    cudaGetSymbolAddress((void**)&qrf, g_qrf);
    cudaGetSymbolAddress((void**)&rtf, g_rtf);
    cudaGetSymbolAddress((void**)&ctxh, g_ctxh);
    cudaGetSymbolAddress((void**)&ctxl, g_ctxl);

    // fused one-time converts
    convAll<<<16896, 256>>>(query, key, value, Wq, Wk, Wv, Wo, rel_emb,
                            inh, inl, qrf, Wh, Wl, rtf);

    // fused Q/K/V projections: one launch, 768 CTAs
    dim3 gqkv(CC / 128, (BB * TT) / 128, 3);
    gemm_qkv<<<gqkv, 256>>>(inh, inl, Wh, Wl, bq, bk, bv, qfh, qfl, kfh, kfl, vtf);

    cudaFuncSetAttribute(flash_mma3, cudaFuncAttributeMaxDynamicSharedMemorySize, FLASH3_SMEM);
    flash_mma3<<<dim3(TT / 128, BB * HH), 256, FLASH3_SMEM>>>(
        qfh, qfl, qrf, kfh, kfl, vtf, rtf, ctxh, ctxl);

    dim3 gout(CC / 128, (BB * TT) / 128);
    gemm_out<<<gout, 256>>>(ctxh, ctxl, Wh + 3*(size_t)NW, Wl + 3*(size_t)NW,
                            bo, out, CC, CC);
}

// round 12
// speedup vs baseline: 1.2646x; 1.1984x over previous
#include <cuda_runtime.h>
#include <cuda_bf16.h>
#include <stdint.h>
#include <math.h>

#define BB 4
#define TT 1024
#define CC 1024
#define HH 16
#define HD 64
#define NEL (BB*TT*CC)          // 4194304
#define NW  (CC*CC)             // 1048576

// ---------------- scratch (device globals: allocation-free) ----------------
__device__ unsigned g_afh[3][NEL/2], g_afl[3][NEL/2];    // q/k/v inputs, A-frag tiles hi/lo
__device__ unsigned g_bfh[4][NW/2],  g_bfl[4][NW/2];     // Wq/Wk/Wv/Wo, B-frag tiles hi/lo
__device__ unsigned g_qfh[NEL/2], g_qfl[NEL/2];          // proj q (x8) flash A-frags
__device__ unsigned g_kfh[NEL/2], g_kfl[NEL/2];          // proj k flash B-frags
__device__ unsigned g_vtf[NEL];                          // proj v tf32 flash B-frags
__device__ unsigned g_qrf[NEL];                          // raw q x8 tf32 flash A-frags
__device__ unsigned g_rtf[32*4096];                      // relpad tf32 B-frag tiles
__device__ unsigned g_ctxfh[NEL/2], g_ctxfl[NEL/2];      // attention out, A-frag tiles hi/lo

// ---------------- helpers ----------------
__device__ __forceinline__ unsigned f2tf32(float x) {
    unsigned u;
    asm("cvt.rna.tf32.f32 %0, %1;" : "=r"(u) : "f"(x));
    return u;
}
__device__ __forceinline__ void mma_tf32(float4& c, const uint4& a, const uint2& b) {
    asm volatile(
        "mma.sync.aligned.m16n8k8.row.col.f32.tf32.tf32.f32 "
        "{%0,%1,%2,%3}, {%4,%5,%6,%7}, {%8,%9}, {%0,%1,%2,%3};"
        : "+f"(c.x), "+f"(c.y), "+f"(c.z), "+f"(c.w)
        : "r"(a.x), "r"(a.y), "r"(a.z), "r"(a.w), "r"(b.x), "r"(b.y));
}
__device__ __forceinline__ void mma_bf16(float4& c, const uint4& a, const uint2& b) {
    asm volatile(
        "mma.sync.aligned.m16n8k16.row.col.f32.bf16.bf16.f32 "
        "{%0,%1,%2,%3}, {%4,%5,%6,%7}, {%8,%9}, {%0,%1,%2,%3};"
        : "+f"(c.x), "+f"(c.y), "+f"(c.z), "+f"(c.w)
        : "r"(a.x), "r"(a.y), "r"(a.z), "r"(a.w), "r"(b.x), "r"(b.y));
}
__device__ __forceinline__ void split_pair(float x, float y, unsigned& hi, unsigned& lo) {
    __nv_bfloat16 hx = __float2bfloat16(x), hy = __float2bfloat16(y);
    __nv_bfloat162 H; H.x = hx; H.y = hy;
    __nv_bfloat162 L;
    L.x = __float2bfloat16(x - __bfloat162float(hx));
    L.y = __float2bfloat16(y - __bfloat162float(hy));
    hi = *reinterpret_cast<unsigned*>(&H);
    lo = *reinterpret_cast<unsigned*>(&L);
}

#define CP16(d, p) asm volatile("cp.async.cg.shared.global [%0], [%1], 16;" :: "r"(d), "l"(p) : "memory")
#define CP_COMMIT() asm volatile("cp.async.commit_group;" ::: "memory")
#define CP_WAIT2()  asm volatile("cp.async.wait_group 2;" ::: "memory")

// A-frag word address for element pair (m, k even): within matrix [M,1024]
__device__ __forceinline__ size_t afrag_addr(int m, int k) {
    int mblk = m >> 7, mr = m & 127, kb = k >> 4, kk = k & 15;
    return (((size_t)mblk * 64 + kb) << 10) + (mr >> 4) * 128
         + ((mr & 7) * 4 + ((kk >> 1) & 3)) * 4 + ((mr >> 3) & 1) + 2 * (kk >> 3);
}
// B-frag word address for element pair (n, k even)
__device__ __forceinline__ size_t bfrag_addr(int n, int k) {
    int nblk = n >> 7, sr = n & 127, kb = k >> 4, kk = k & 15;
    return (((size_t)nblk * 64 + kb) << 10) + (sr >> 3) * 64
         + ((sr & 7) * 4 + ((kk >> 1) & 3)) * 2 + (kk >> 3);
}

// ---------------- fused one-time converts ----------------
__global__ void convAll(const float* __restrict__ q, const float* __restrict__ k,
                        const float* __restrict__ v,
                        const float* __restrict__ Wq, const float* __restrict__ Wk,
                        const float* __restrict__ Wv, const float* __restrict__ Wo,
                        const float* __restrict__ rel_emb,
                        unsigned* __restrict__ afh, unsigned* __restrict__ afl,
                        unsigned* __restrict__ qrf,
                        unsigned* __restrict__ bfh, unsigned* __restrict__ bfl,
                        unsigned* __restrict__ rtf)
{
    int blk = blockIdx.x;
    if (blk < 12288) {
        int arr = blk >> 12;
        int i = ((blk & 4095) << 8) + threadIdx.x;
        const float* src = arr == 0 ? q : (arr == 1 ? k : v);
        float4 v4 = ((const float4*)src)[i];
        unsigned h0, l0, h1, l1;
        split_pair(v4.x, v4.y, h0, l0);
        split_pair(v4.z, v4.w, h1, l1);
        int e = i * 4;
        int m = e >> 10, k0 = e & 1023;
        size_t base = (size_t)arr * (NEL/2) + afrag_addr(m, k0);
        afh[base] = h0; afh[base + 4] = h1;
        afl[base] = l0; afl[base + 4] = l1;
        if (arr == 0) {
            int hh_ = k0 >> 6, d = k0 & 63;
            int b_ = m >> 10, tt = (m >> 7) & 7, mr = m & 127;
            size_t blko = ((size_t)((b_ * 8 + tt) * 16 + hh_)) << 13;
            int qb = ((d >> 3) * 8 + (mr >> 4)) * 128 + (mr & 7) * 16
                   + ((mr >> 3) & 1) + 2 * ((d >> 2) & 1);
            qrf[blko + qb +  0] = f2tf32(8.f * v4.x);
            qrf[blko + qb +  4] = f2tf32(8.f * v4.y);
            qrf[blko + qb +  8] = f2tf32(8.f * v4.z);
            qrf[blko + qb + 12] = f2tf32(8.f * v4.w);
        }
    } else if (blk < 16384) {
        int wblk = blk - 12288;
        int arr = wblk >> 10;
        int i = ((wblk & 1023) << 8) + threadIdx.x;
        const float* src = arr == 0 ? Wq : (arr == 1 ? Wk : (arr == 2 ? Wv : Wo));
        float4 v4 = ((const float4*)src)[i];
        unsigned h0, l0, h1, l1;
        split_pair(v4.x, v4.y, h0, l0);
        split_pair(v4.z, v4.w, h1, l1);
        int e = i * 4;
        int n = e >> 10, k0 = e & 1023;
        size_t base = (size_t)arr * (NW/2) + bfrag_addr(n, k0);
        bfh[base] = h0; bfh[base + 2] = h1;
        bfl[base] = l0; bfl[base + 2] = l1;
    } else {
        int e = ((blk - 16384) << 8) + threadIdx.x;
        int tt = e >> 12, rem = e & 4095;
        int ul = rem >> 6, d = rem & 63;
        int u = tt * 64 + ul;
        int src = u - 24;
        src = src < 0 ? 0 : (src > 1998 ? 1998 : src);
        int addr = tt * 4096 + ((d >> 3) * 8 + (ul >> 3)) * 64
                 + ((ul & 7) * 4 + (d & 3)) * 2 + ((d >> 2) & 1);
        rtf[addr] = f2tf32(rel_emb[src * HD + d]);
    }
}

// ---------------- cp.async 4-stage GEMM core (128x128 block, K=1024) ----------------
// Frag-ordered operands in gmem; stage = [Ah 4KB | Al 4KB | Bh 4KB | Bl 4KB].
__device__ __forceinline__ void gemm_core(const unsigned* __restrict__ Ahp,
                                          const unsigned* __restrict__ Alp,
                                          const unsigned* __restrict__ Bhp,
                                          const unsigned* __restrict__ Blp,
                                          unsigned* sm, float4 (&acc)[4][4])
{
    const int tid = threadIdx.x;
    const int lane = tid & 31;
    const int warp = tid >> 5;
    const int wrow = warp & 1, wcol = warp >> 1;
    const unsigned sbase = (unsigned)__cvta_generic_to_shared(sm);

#define GISSUE(kb_, s_) { \
        unsigned dd = sbase + (s_) * 16384 + (tid << 4); \
        int off = ((kb_) << 10) + (tid << 2); \
        CP16(dd,          Ahp + off); \
        CP16(dd + 4096,   Alp + off); \
        CP16(dd + 8192,   Bhp + off); \
        CP16(dd + 12288,  Blp + off); \
    }

#pragma unroll
    for (int s = 0; s < 3; s++) { GISSUE(s, s); CP_COMMIT(); }

    for (int kb = 0; kb < 64; kb++) {
        CP_WAIT2();
        __syncthreads();
        if (kb < 61) GISSUE(kb + 3, (kb + 3) & 3);
        CP_COMMIT();

        const unsigned* st = sm + (kb & 3) * 4096;
        uint4 ah[4], al[4];
        uint2 bh[4], bl[4];
#pragma unroll
        for (int i = 0; i < 4; i++) {
            ah[i] = *(const uint4*)&st[(wrow * 4 + i) * 128 + lane * 4];
            al[i] = *(const uint4*)&st[1024 + (wrow * 4 + i) * 128 + lane * 4];
        }
#pragma unroll
        for (int j = 0; j < 4; j++) {
            bh[j] = *(const uint2*)&st[2048 + (wcol * 4 + j) * 64 + lane * 2];
            bl[j] = *(const uint2*)&st[3072 + (wcol * 4 + j) * 64 + lane * 2];
        }
#pragma unroll
        for (int i = 0; i < 4; i++)
#pragma unroll
            for (int j = 0; j < 4; j++) {
                mma_bf16(acc[i][j], ah[i], bl[j]);
                mma_bf16(acc[i][j], al[i], bh[j]);
                mma_bf16(acc[i][j], ah[i], bh[j]);
            }
    }
#undef GISSUE
}

#define GEMM_SMEM 65536

// ========== fused Q/K/V projection GEMM (blockIdx.z selects matrix + epilogue) ==========
__global__ __launch_bounds__(256)
void gemm_qkv(const unsigned* __restrict__ afh, const unsigned* __restrict__ afl,
              const unsigned* __restrict__ bfh, const unsigned* __restrict__ bfl,
              const float* __restrict__ bq, const float* __restrict__ bk,
              const float* __restrict__ bv,
              unsigned* __restrict__ qfh, unsigned* __restrict__ qfl,
              unsigned* __restrict__ kfh, unsigned* __restrict__ kfl,
              unsigned* __restrict__ vtf)
{
    extern __shared__ unsigned smg[];
    const int z = blockIdx.z;
    const int bm = blockIdx.y * 128, bn = blockIdx.x * 128;
    const int lane = threadIdx.x & 31, warp = threadIdx.x >> 5;
    const int wrow = warp & 1, wcol = warp >> 1;

    float4 acc[4][4];
#pragma unroll
    for (int i = 0; i < 4; i++)
#pragma unroll
        for (int j = 0; j < 4; j++) acc[i][j] = make_float4(0.f, 0.f, 0.f, 0.f);

    gemm_core(afh + (size_t)z * (NEL/2) + ((size_t)(bm >> 7) << 16),
              afl + (size_t)z * (NEL/2) + ((size_t)(bm >> 7) << 16),
              bfh + (size_t)z * (NW/2)  + ((size_t)(bn >> 7) << 16),
              bfl + (size_t)z * (NW/2)  + ((size_t)(bn >> 7) << 16),
              smg, acc);

    const float* bias = z == 0 ? bq : (z == 1 ? bk : bv);
    const float scale = z == 0 ? 8.0f : 1.0f;
    const int g = lane >> 2, tig = lane & 3;
#pragma unroll
    for (int i = 0; i < 4; i++) {
#pragma unroll
        for (int j = 0; j < 4; j++) {
            int m0 = bm + wrow * 64 + i * 16 + g;
            int n0 = bn + wcol * 32 + j * 8 + tig * 2;
            float b0 = bias[n0], b1 = bias[n0 + 1];
            float x0 = (acc[i][j].x + b0) * scale, x1 = (acc[i][j].y + b1) * scale;
            float x2 = (acc[i][j].z + b0) * scale, x3 = (acc[i][j].w + b1) * scale;
            int b_ = m0 >> 10, hh_ = n0 >> 6, d = n0 & 63;
            if (z == 0) {
                int tt = (m0 >> 7) & 7, mr = m0 & 127;
                size_t blk = ((size_t)((b_ * 8 + tt) * 16 + hh_)) << 12;
                int addr = ((d >> 4) * 8 + (mr >> 4)) * 128
                         + ((mr & 7) * 4 + ((d >> 1) & 3)) * 4
                         + ((mr >> 3) & 1) + 2 * ((d >> 3) & 1);
                unsigned hw, lw;
                split_pair(x0, x1, hw, lw);
                qfh[blk + addr] = hw; qfl[blk + addr] = lw;
                split_pair(x2, x3, hw, lw);
                qfh[blk + addr + 1] = hw; qfl[blk + addr + 1] = lw;
            } else if (z == 1) {
                int stt = (m0 >> 6) & 15, sr = m0 & 63;
                size_t blk = ((size_t)((b_ * 16 + stt) * 16 + hh_)) << 11;
                int addr = ((d >> 4) * 8 + (sr >> 3)) * 64
                         + ((sr & 7) * 4 + ((d >> 1) & 3)) * 2 + ((d >> 3) & 1);
                unsigned hw, lw;
                split_pair(x0, x1, hw, lw);
                kfh[blk + addr] = hw; kfl[blk + addr] = lw;
                split_pair(x2, x3, hw, lw);
                kfh[blk + addr + 64] = hw; kfl[blk + addr + 64] = lw;
            } else {
                int stt = (m0 >> 6) & 15, sr = m0 & 63;
                size_t blk = ((size_t)((b_ * 16 + stt) * 16 + hh_)) << 12;
                int a00 = ((sr >> 3) * 8 + (d >> 3)) * 64
                        + ((d & 7) * 4 + (sr & 3)) * 2 + ((sr >> 2) & 1);
                vtf[blk + a00]           = f2tf32(x0);
                vtf[blk + a00 + 8]       = f2tf32(x1);
                vtf[blk + a00 + 512]     = f2tf32(x2);
                vtf[blk + a00 + 8 + 512] = f2tf32(x3);
            }
        }
    }
}

// ========== output projection GEMM (fp32 row-major out) ==========
__global__ __launch_bounds__(256)
void gemm_out(const unsigned* __restrict__ ctxfh, const unsigned* __restrict__ ctxfl,
              const unsigned* __restrict__ bfh, const unsigned* __restrict__ bfl,
              const float* __restrict__ bias, float* __restrict__ o0)
{
    extern __shared__ unsigned smg[];
    const int bm = blockIdx.y * 128, bn = blockIdx.x * 128;
    const int lane = threadIdx.x & 31, warp = threadIdx.x >> 5;
    const int wrow = warp & 1, wcol = warp >> 1;

    float4 acc[4][4];
#pragma unroll
    for (int i = 0; i < 4; i++)
#pragma unroll
        for (int j = 0; j < 4; j++) acc[i][j] = make_float4(0.f, 0.f, 0.f, 0.f);

    gemm_core(ctxfh + ((size_t)(bm >> 7) << 16),
              ctxfl + ((size_t)(bm >> 7) << 16),
              bfh + ((size_t)(bn >> 7) << 16),
              bfl + ((size_t)(bn >> 7) << 16),
              smg, acc);

    const int g = lane >> 2, tig = lane & 3;
#pragma unroll
    for (int i = 0; i < 4; i++) {
#pragma unroll
        for (int j = 0; j < 4; j++) {
            int m0 = bm + wrow * 64 + i * 16 + g;
            int n0 = bn + wcol * 32 + j * 8 + tig * 2;
            float b0 = bias[n0], b1 = bias[n0 + 1];
            size_t i0 = (size_t)m0 * CC + n0, i1 = (size_t)(m0 + 8) * CC + n0;
            *(float2*)(o0 + i0) = make_float2(acc[i][j].x + b0, acc[i][j].y + b1);
            *(float2*)(o0 + i1) = make_float2(acc[i][j].z + b0, acc[i][j].w + b1);
        }
    }
}

// ============== flash attention (round-6 config; epilogue -> A-frag ctx) ==============
#define ZP2 66
#define FLASH3_WORDS (4096+4096+8192+2048+2048+4096+12288+8192+128*ZP2)
#define FLASH3_SMEM (FLASH3_WORDS * 4)

__global__ __launch_bounds__(256)
void flash_mma3(const unsigned* __restrict__ qfh, const unsigned* __restrict__ qfl,
                const unsigned* __restrict__ qrg,
                const unsigned* __restrict__ kfh, const unsigned* __restrict__ kfl,
                const unsigned* __restrict__ vtf, const unsigned* __restrict__ rtf,
                unsigned* __restrict__ ctxfh, unsigned* __restrict__ ctxfl)
{
    extern __shared__ unsigned smu[];
    unsigned* qf_h = smu;
    unsigned* qf_l = qf_h + 4096;
    unsigned* qrf  = qf_l + 4096;
    unsigned* kf_h = qrf + 8192;
    unsigned* kf_l = kf_h + 2048;
    unsigned* vf   = kf_l + 2048;
    unsigned* rf   = vf + 4096;
    unsigned* pfs  = rf + 12288;
    float* Zs      = (float*)(pfs + 8192);

    const int tid = threadIdx.x;
    const int lane = tid & 31;
    const int w = tid >> 5;
    const int g = lane >> 2, tig = lane & 3;
    const int b = blockIdx.y >> 4, hq = blockIdx.y & 15;
    const int bx = blockIdx.x, t0 = bx * 128;
    unsigned* pf = pfs + w * 1024;
    const int m0 = w * 16 + g, m1 = m0 + 8;

    {
        size_t qblk = ((size_t)((b * 8 + bx) * 16 + hq));
        const uint4* qh4 = (const uint4*)(qfh + (qblk << 12));
        const uint4* ql4 = (const uint4*)(qfl + (qblk << 12));
        const uint4* qr4 = (const uint4*)(qrg + (qblk << 13));
#pragma unroll
        for (int x = 0; x < 4; x++) ((uint4*)qf_h)[tid + 256 * x] = qh4[tid + 256 * x];
#pragma unroll
        for (int x = 0; x < 4; x++) ((uint4*)qf_l)[tid + 256 * x] = ql4[tid + 256 * x];
#pragma unroll
        for (int x = 0; x < 8; x++) ((uint4*)qrf)[tid + 256 * x] = qr4[tid + 256 * x];
    }

    float m_i[2] = {-1e30f, -1e30f}, l_i[2] = {0.f, 0.f};
    float4 o[8];
#pragma unroll
    for (int j = 0; j < 8; j++) o[j] = make_float4(0.f, 0.f, 0.f, 0.f);

    for (int i = 0; i < 16; i++) {
        int T = i - 2 * bx + 14;
        __syncthreads();

        {
            size_t kb_ = (size_t)((b * 16 + i) * 16 + hq);
            const uint4* kh4 = (const uint4*)(kfh + (kb_ << 11));
            const uint4* kl4 = (const uint4*)(kfl + (kb_ << 11));
            const uint4* v4  = (const uint4*)(vtf + (kb_ << 12));
#pragma unroll
            for (int x = 0; x < 2; x++) ((uint4*)kf_h)[tid + 256 * x] = kh4[tid + 256 * x];
#pragma unroll
            for (int x = 0; x < 2; x++) ((uint4*)kf_l)[tid + 256 * x] = kl4[tid + 256 * x];
#pragma unroll
            for (int x = 0; x < 4; x++) ((uint4*)vf)[tid + 256 * x] = v4[tid + 256 * x];
            if (i == 0) {
#pragma unroll
                for (int it = 0; it < 2; it++) {
                    const uint4* rs = (const uint4*)(rtf + (size_t)(T + it) * 4096);
                    uint4* rd = (uint4*)(rf + ((T + it) % 3) * 4096);
#pragma unroll
                    for (int x = 0; x < 4; x++) rd[tid + 256 * x] = rs[tid + 256 * x];
                }
            }
            {
                const uint4* rs = (const uint4*)(rtf + (size_t)(T + 2) * 4096);
                uint4* rd = (uint4*)(rf + ((T + 2) % 3) * 4096);
#pragma unroll
                for (int x = 0; x < 4; x++) rd[tid + 256 * x] = rs[tid + 256 * x];
            }
        }
        __syncthreads();

        {
            const unsigned* rslot[3] = { rf + (T % 3) * 4096,
                                         rf + ((T + 1) % 3) * 4096,
                                         rf + ((T + 2) % 3) * 4096 };
            float4 zc[10];
#pragma unroll
            for (int j = 0; j < 10; j++) zc[j] = make_float4(0.f, 0.f, 0.f, 0.f);
#pragma unroll
            for (int ks = 0; ks < 8; ks++) {
                uint4 a = *(const uint4*)(qrf + (ks * 8 + w) * 128 + lane * 4);
#pragma unroll
                for (int j = 0; j < 10; j++) {
                    int nt = 14 - 2 * w + j;
                    uint2 bb = *(const uint2*)(rslot[nt >> 3] + (ks * 8 + (nt & 7)) * 64 + lane * 2);
                    mma_tf32(zc[j], a, bb);
                }
            }
#pragma unroll
            for (int j = 0; j < 10; j++) {
                int u = (14 - 2 * w + j) * 8 + 2 * tig;
                int s = u + m0 - 127;
                if ((unsigned)s < 64u)       Zs[m0 * ZP2 + s]     = zc[j].x;
                if ((unsigned)(s + 1) < 64u) Zs[m0 * ZP2 + s + 1] = zc[j].y;
                int s2 = s + 8;
                if ((unsigned)s2 < 64u)       Zs[m1 * ZP2 + s2]     = zc[j].z;
                if ((unsigned)(s2 + 1) < 64u) Zs[m1 * ZP2 + s2 + 1] = zc[j].w;
            }
        }
        __syncwarp();

        float4 sc[8];
#pragma unroll
        for (int j = 0; j < 8; j++) sc[j] = make_float4(0.f, 0.f, 0.f, 0.f);
#pragma unroll
        for (int kb = 0; kb < 4; kb++) {
            uint4 ah = *(const uint4*)(qf_h + (kb * 8 + w) * 128 + lane * 4);
            uint4 al = *(const uint4*)(qf_l + (kb * 8 + w) * 128 + lane * 4);
#pragma unroll
            for (int nt = 0; nt < 8; nt++) {
                uint2 bh = *(const uint2*)(kf_h + (kb * 8 + nt) * 64 + lane * 2);
                uint2 bl = *(const uint2*)(kf_l + (kb * 8 + nt) * 64 + lane * 2);
                mma_bf16(sc[nt], ah, bl);
                mma_bf16(sc[nt], al, bh);
                mma_bf16(sc[nt], ah, bh);
            }
        }

        float v0[16], v1[16];
#pragma unroll
        for (int nt = 0; nt < 8; nt++) {
            int s = nt * 8 + 2 * tig;
            v0[2*nt]   = sc[nt].x + Zs[m0 * ZP2 + s];
            v0[2*nt+1] = sc[nt].y + Zs[m0 * ZP2 + s + 1];
            v1[2*nt]   = sc[nt].z + Zs[m1 * ZP2 + s];
            v1[2*nt+1] = sc[nt].w + Zs[m1 * ZP2 + s + 1];
        }
        float lm0 = v0[0], lm1 = v1[0];
#pragma unroll
        for (int e = 1; e < 16; e++) { lm0 = fmaxf(lm0, v0[e]); lm1 = fmaxf(lm1, v1[e]); }
        lm0 = fmaxf(lm0, __shfl_xor_sync(~0u, lm0, 1));
        lm0 = fmaxf(lm0, __shfl_xor_sync(~0u, lm0, 2));
        lm1 = fmaxf(lm1, __shfl_xor_sync(~0u, lm1, 1));
        lm1 = fmaxf(lm1, __shfl_xor_sync(~0u, lm1, 2));
        float mn0 = fmaxf(m_i[0], lm0), mn1 = fmaxf(m_i[1], lm1);
        float al0 = __expf(m_i[0] - mn0), al1 = __expf(m_i[1] - mn1);
        m_i[0] = mn0; m_i[1] = mn1;
        float rs0 = 0.f, rs1 = 0.f;
#pragma unroll
        for (int nt = 0; nt < 8; nt++) {
            int s = nt * 8 + 2 * tig;
            float p00 = __expf(v0[2*nt]   - mn0);
            float p01 = __expf(v0[2*nt+1] - mn0);
            float p10 = __expf(v1[2*nt]   - mn1);
            float p11 = __expf(v1[2*nt+1] - mn1);
            rs0 += p00 + p01; rs1 += p10 + p11;
            int base = nt * 128 + (g * 4 + (s & 3)) * 4 + 2 * ((s >> 2) & 1);
            pf[base]     = f2tf32(p00);
            pf[base + 1] = f2tf32(p10);
            pf[base + 4] = f2tf32(p01);
            pf[base + 5] = f2tf32(p11);
        }
        rs0 += __shfl_xor_sync(~0u, rs0, 1); rs0 += __shfl_xor_sync(~0u, rs0, 2);
        rs1 += __shfl_xor_sync(~0u, rs1, 1); rs1 += __shfl_xor_sync(~0u, rs1, 2);
        l_i[0] = l_i[0] * al0 + rs0;
        l_i[1] = l_i[1] * al1 + rs1;
#pragma unroll
        for (int j = 0; j < 8; j++) {
            o[j].x *= al0; o[j].y *= al0; o[j].z *= al1; o[j].w *= al1;
        }
        __syncwarp();

#pragma unroll
        for (int ks = 0; ks < 8; ks++) {
            uint4 a = *(const uint4*)(pf + ks * 128 + lane * 4);
#pragma unroll
            for (int nt = 0; nt < 8; nt++) {
                uint2 bb = *(const uint2*)(vf + (ks * 8 + nt) * 64 + lane * 2);
                mma_tf32(o[nt], a, bb);
            }
        }
    }

    // epilogue: normalize, split, store in GEMM A-frag layout
    float inv0 = 1.f / l_i[0], inv1 = 1.f / l_i[1];
#pragma unroll
    for (int nt = 0; nt < 8; nt++) {
        int c = hq * HD + nt * 8 + 2 * tig;
        int mg0 = b * TT + t0 + m0, mg1 = b * TT + t0 + m1;
        unsigned hh, ll;
        split_pair(o[nt].x * inv0, o[nt].y * inv0, hh, ll);
        size_t a0 = afrag_addr(mg0, c);
        ctxfh[a0] = hh; ctxfl[a0] = ll;
        split_pair(o[nt].z * inv1, o[nt].w * inv1, hh, ll);
        size_t a1 = afrag_addr(mg1, c);
        ctxfh[a1] = hh; ctxfl[a1] = ll;
    }
}

// ------------------------------ launch ------------------------------
extern "C" void kernel_launch(void* const* d_in, const int* in_sizes, int n_in,
                              void* d_out, int out_size)
{
    const float* query   = (const float*)d_in[0];
    const float* key     = (const float*)d_in[1];
    const float* value   = (const float*)d_in[2];
    const float* Wq      = (const float*)d_in[3];
    const float* bq      = (const float*)d_in[4];
    const float* Wk      = (const float*)d_in[5];
    const float* bk      = (const float*)d_in[6];
    const float* Wv      = (const float*)d_in[7];
    const float* bv      = (const float*)d_in[8];
    const float* Wo      = (const float*)d_in[9];
    const float* bo      = (const float*)d_in[10];
    const float* rel_emb = (const float*)d_in[11];
    float* out = (float*)d_out;

    unsigned *afh, *afl, *bfh, *bfl, *qfh, *qfl, *kfh, *kfl, *vtf, *qrf, *rtf, *ctxfh, *ctxfl;
    cudaGetSymbolAddress((void**)&afh, g_afh);
    cudaGetSymbolAddress((void**)&afl, g_afl);
    cudaGetSymbolAddress((void**)&bfh, g_bfh);
    cudaGetSymbolAddress((void**)&bfl, g_bfl);
    cudaGetSymbolAddress((void**)&qfh, g_qfh);
    cudaGetSymbolAddress((void**)&qfl, g_qfl);
    cudaGetSymbolAddress((void**)&kfh, g_kfh);
    cudaGetSymbolAddress((void**)&kfl, g_kfl);
    cudaGetSymbolAddress((void**)&vtf, g_vtf);
    cudaGetSymbolAddress((void**)&qrf, g_qrf);
    cudaGetSymbolAddress((void**)&rtf, g_rtf);
    cudaGetSymbolAddress((void**)&ctxfh, g_ctxfh);
    cudaGetSymbolAddress((void**)&ctxfl, g_ctxfl);

    convAll<<<16896, 256>>>(query, key, value, Wq, Wk, Wv, Wo, rel_emb,
                            afh, afl, qrf, bfh, bfl, rtf);

    cudaFuncSetAttribute(gemm_qkv, cudaFuncAttributeMaxDynamicSharedMemorySize, GEMM_SMEM);
    cudaFuncSetAttribute(gemm_out, cudaFuncAttributeMaxDynamicSharedMemorySize, GEMM_SMEM);

    dim3 gqkv(CC / 128, (BB * TT) / 128, 3);
    gemm_qkv<<<gqkv, 256, GEMM_SMEM>>>(afh, afl, bfh, bfl, bq, bk, bv,
                                       qfh, qfl, kfh, kfl, vtf);

    cudaFuncSetAttribute(flash_mma3, cudaFuncAttributeMaxDynamicSharedMemorySize, FLASH3_SMEM);
    flash_mma3<<<dim3(TT / 128, BB * HH), 256, FLASH3_SMEM>>>(
        qfh, qfl, qrf, kfh, kfl, vtf, rtf, ctxfh, ctxfl);

    dim3 gout(CC / 128, (BB * TT) / 128);
    gemm_out<<<gout, 256, GEMM_SMEM>>>(ctxfh, ctxfl, bfh + 3*(size_t)(NW/2),
                                       bfl + 3*(size_t)(NW/2), bo, out);
}

// round 14
// speedup vs baseline: 1.2889x; 1.0192x over previous
#include <cuda_runtime.h>
#include <cuda_bf16.h>
#include <stdint.h>
#include <math.h>

#define BB 4
#define TT 1024
#define CC 1024
#define HH 16
#define HD 64
#define NEL (BB*TT*CC)          // 4194304
#define NW  (CC*CC)             // 1048576

// ---------------- scratch (device globals: allocation-free) ----------------
__device__ unsigned g_afh[3][NEL/2], g_afl[3][NEL/2];    // q/k/v inputs, A-frag tiles hi/lo
__device__ unsigned g_bfh[4][NW/2],  g_bfl[4][NW/2];     // Wq/Wk/Wv/Wo, B-frag tiles hi/lo
__device__ unsigned g_qfh[NEL/2], g_qfl[NEL/2];          // proj q (x8) flash A-frags
__device__ unsigned g_kfh[NEL/2], g_kfl[NEL/2];          // proj k flash B-frags
__device__ unsigned g_vtf[NEL];                          // proj v tf32 flash B-frags
__device__ unsigned g_qrf[NEL];                          // raw q x8 tf32 flash A-frags
__device__ unsigned g_rtf[32*4096];                      // relpad tf32 B-frag tiles
__device__ unsigned g_ctxfh[NEL/2], g_ctxfl[NEL/2];      // attention out, A-frag tiles hi/lo

// ---------------- helpers ----------------
__device__ __forceinline__ unsigned f2tf32(float x) {
    unsigned u;
    asm("cvt.rna.tf32.f32 %0, %1;" : "=r"(u) : "f"(x));
    return u;
}
__device__ __forceinline__ void mma_tf32(float4& c, const uint4& a, const uint2& b) {
    asm volatile(
        "mma.sync.aligned.m16n8k8.row.col.f32.tf32.tf32.f32 "
        "{%0,%1,%2,%3}, {%4,%5,%6,%7}, {%8,%9}, {%0,%1,%2,%3};"
        : "+f"(c.x), "+f"(c.y), "+f"(c.z), "+f"(c.w)
        : "r"(a.x), "r"(a.y), "r"(a.z), "r"(a.w), "r"(b.x), "r"(b.y));
}
__device__ __forceinline__ void mma_bf16(float4& c, const uint4& a, const uint2& b) {
    asm volatile(
        "mma.sync.aligned.m16n8k16.row.col.f32.bf16.bf16.f32 "
        "{%0,%1,%2,%3}, {%4,%5,%6,%7}, {%8,%9}, {%0,%1,%2,%3};"
        : "+f"(c.x), "+f"(c.y), "+f"(c.z), "+f"(c.w)
        : "r"(a.x), "r"(a.y), "r"(a.z), "r"(a.w), "r"(b.x), "r"(b.y));
}
__device__ __forceinline__ void split_pair(float x, float y, unsigned& hi, unsigned& lo) {
    __nv_bfloat16 hx = __float2bfloat16(x), hy = __float2bfloat16(y);
    __nv_bfloat162 H; H.x = hx; H.y = hy;
    __nv_bfloat162 L;
    L.x = __float2bfloat16(x - __bfloat162float(hx));
    L.y = __float2bfloat16(y - __bfloat162float(hy));
    hi = *reinterpret_cast<unsigned*>(&H);
    lo = *reinterpret_cast<unsigned*>(&L);
}

#define CP16(d, p) asm volatile("cp.async.cg.shared.global [%0], [%1], 16;" :: "r"(d), "l"(p) : "memory")
#define CP_COMMIT() asm volatile("cp.async.commit_group;" ::: "memory")
#define CP_WAIT1()  asm volatile("cp.async.wait_group 1;" ::: "memory")

// A-frag word address for element pair (m, k even): within matrix [M,1024]
__device__ __forceinline__ size_t afrag_addr(int m, int k) {
    int mblk = m >> 7, mr = m & 127, kb = k >> 4, kk = k & 15;
    return (((size_t)mblk * 64 + kb) << 10) + (mr >> 4) * 128
         + ((mr & 7) * 4 + ((kk >> 1) & 3)) * 4 + ((mr >> 3) & 1) + 2 * (kk >> 3);
}
// B-frag word address for element pair (n, k even)
__device__ __forceinline__ size_t bfrag_addr(int n, int k) {
    int nblk = n >> 7, sr = n & 127, kb = k >> 4, kk = k & 15;
    return (((size_t)nblk * 64 + kb) << 10) + (sr >> 3) * 64
         + ((sr & 7) * 4 + ((kk >> 1) & 3)) * 2 + (kk >> 3);
}

// ---------------- fused one-time converts ----------------
__global__ void convAll(const float* __restrict__ q, const float* __restrict__ k,
                        const float* __restrict__ v,
                        const float* __restrict__ Wq, const float* __restrict__ Wk,
                        const float* __restrict__ Wv, const float* __restrict__ Wo,
                        const float* __restrict__ rel_emb,
                        unsigned* __restrict__ afh, unsigned* __restrict__ afl,
                        unsigned* __restrict__ qrf,
                        unsigned* __restrict__ bfh, unsigned* __restrict__ bfl,
                        unsigned* __restrict__ rtf)
{
    int blk = blockIdx.x;
    if (blk < 12288) {
        int arr = blk >> 12;
        int i = ((blk & 4095) << 8) + threadIdx.x;
        const float* src = arr == 0 ? q : (arr == 1 ? k : v);
        float4 v4 = ((const float4*)src)[i];
        unsigned h0, l0, h1, l1;
        split_pair(v4.x, v4.y, h0, l0);
        split_pair(v4.z, v4.w, h1, l1);
        int e = i * 4;
        int m = e >> 10, k0 = e & 1023;
        size_t base = (size_t)arr * (NEL/2) + afrag_addr(m, k0);
        afh[base] = h0; afh[base + 4] = h1;
        afl[base] = l0; afl[base + 4] = l1;
        if (arr == 0) {
            int hh_ = k0 >> 6, d = k0 & 63;
            int b_ = m >> 10, tt = (m >> 7) & 7, mr = m & 127;
            size_t blko = ((size_t)((b_ * 8 + tt) * 16 + hh_)) << 13;
            int qb = ((d >> 3) * 8 + (mr >> 4)) * 128 + (mr & 7) * 16
                   + ((mr >> 3) & 1) + 2 * ((d >> 2) & 1);
            qrf[blko + qb +  0] = f2tf32(8.f * v4.x);
            qrf[blko + qb +  4] = f2tf32(8.f * v4.y);
            qrf[blko + qb +  8] = f2tf32(8.f * v4.z);
            qrf[blko + qb + 12] = f2tf32(8.f * v4.w);
        }
    } else if (blk < 16384) {
        int wblk = blk - 12288;
        int arr = wblk >> 10;
        int i = ((wblk & 1023) << 8) + threadIdx.x;
        const float* src = arr == 0 ? Wq : (arr == 1 ? Wk : (arr == 2 ? Wv : Wo));
        float4 v4 = ((const float4*)src)[i];
        unsigned h0, l0, h1, l1;
        split_pair(v4.x, v4.y, h0, l0);
        split_pair(v4.z, v4.w, h1, l1);
        int e = i * 4;
        int n = e >> 10, k0 = e & 1023;
        size_t base = (size_t)arr * (NW/2) + bfrag_addr(n, k0);
        bfh[base] = h0; bfh[base + 2] = h1;
        bfl[base] = l0; bfl[base + 2] = l1;
    } else {
        int e = ((blk - 16384) << 8) + threadIdx.x;
        int tt = e >> 12, rem = e & 4095;
        int ul = rem >> 6, d = rem & 63;
        int u = tt * 64 + ul;
        int src = u - 24;
        src = src < 0 ? 0 : (src > 1998 ? 1998 : src);
        int addr = tt * 4096 + ((d >> 3) * 8 + (ul >> 3)) * 64
                 + ((ul & 7) * 4 + (d & 3)) * 2 + ((d >> 2) & 1);
        rtf[addr] = f2tf32(rel_emb[src * HD + d]);
    }
}

// ---------------- cp.async 3-stage GEMM core (128x128 block, K=1024, 2 CTA/SM) ----
__device__ __forceinline__ void gemm_core(const unsigned* __restrict__ Ahp,
                                          const unsigned* __restrict__ Alp,
                                          const unsigned* __restrict__ Bhp,
                                          const unsigned* __restrict__ Blp,
                                          unsigned* sm, float4 (&acc)[4][4])
{
    const int tid = threadIdx.x;
    const int lane = tid & 31;
    const int warp = tid >> 5;
    const int wrow = warp & 1, wcol = warp >> 1;
    const unsigned sbase = (unsigned)__cvta_generic_to_shared(sm);

#define GISSUE(kb_, s_) { \
        unsigned dd = sbase + (s_) * 16384 + (tid << 4); \
        int off = ((kb_) << 10) + (tid << 2); \
        CP16(dd,          Ahp + off); \
        CP16(dd + 4096,   Alp + off); \
        CP16(dd + 8192,   Bhp + off); \
        CP16(dd + 12288,  Blp + off); \
    }

    GISSUE(0, 0); CP_COMMIT();
    GISSUE(1, 1); CP_COMMIT();

    int st3 = 0;          // (kb % 3)
    int st3n = 2;         // ((kb+2) % 3)
    for (int kb = 0; kb < 64; kb++) {
        CP_WAIT1();
        __syncthreads();
        if (kb < 62) GISSUE(kb + 2, st3n);
        CP_COMMIT();

        const unsigned* st = sm + st3 * 4096;
        uint4 ah[4], al[4];
        uint2 bh[4], bl[4];
#pragma unroll
        for (int i = 0; i < 4; i++) {
            ah[i] = *(const uint4*)&st[(wrow * 4 + i) * 128 + lane * 4];
            al[i] = *(const uint4*)&st[1024 + (wrow * 4 + i) * 128 + lane * 4];
        }
#pragma unroll
        for (int j = 0; j < 4; j++) {
            bh[j] = *(const uint2*)&st[2048 + (wcol * 4 + j) * 64 + lane * 2];
            bl[j] = *(const uint2*)&st[3072 + (wcol * 4 + j) * 64 + lane * 2];
        }
#pragma unroll
        for (int i = 0; i < 4; i++)
#pragma unroll
            for (int j = 0; j < 4; j++) {
                mma_bf16(acc[i][j], ah[i], bl[j]);
                mma_bf16(acc[i][j], al[i], bh[j]);
                mma_bf16(acc[i][j], ah[i], bh[j]);
            }
        st3 = st3 == 2 ? 0 : st3 + 1;
        st3n = st3n == 2 ? 0 : st3n + 1;
    }
#undef GISSUE
}

#define GEMM_SMEM 49152

// ========== fused Q/K/V projection GEMM (blockIdx.z selects matrix + epilogue) ==========
__global__ __launch_bounds__(256, 2)
void gemm_qkv(const unsigned* __restrict__ afh, const unsigned* __restrict__ afl,
              const unsigned* __restrict__ bfh, const unsigned* __restrict__ bfl,
              const float* __restrict__ bq, const float* __restrict__ bk,
              const float* __restrict__ bv,
              unsigned* __restrict__ qfh, unsigned* __restrict__ qfl,
              unsigned* __restrict__ kfh, unsigned* __restrict__ kfl,
              unsigned* __restrict__ vtf)
{
    extern __shared__ unsigned smg[];
    const int z = blockIdx.z;
    const int bm = blockIdx.y * 128, bn = blockIdx.x * 128;
    const int lane = threadIdx.x & 31, warp = threadIdx.x >> 5;
    const int wrow = warp & 1, wcol = warp >> 1;

    float4 acc[4][4];
#pragma unroll
    for (int i = 0; i < 4; i++)
#pragma unroll
        for (int j = 0; j < 4; j++) acc[i][j] = make_float4(0.f, 0.f, 0.f, 0.f);

    gemm_core(afh + (size_t)z * (NEL/2) + ((size_t)(bm >> 7) << 16),
              afl + (size_t)z * (NEL/2) + ((size_t)(bm >> 7) << 16),
              bfh + (size_t)z * (NW/2)  + ((size_t)(bn >> 7) << 16),
              bfl + (size_t)z * (NW/2)  + ((size_t)(bn >> 7) << 16),
              smg, acc);

    const float* bias = z == 0 ? bq : (z == 1 ? bk : bv);
    const float scale = z == 0 ? 8.0f : 1.0f;
    const int g = lane >> 2, tig = lane & 3;
#pragma unroll
    for (int i = 0; i < 4; i++) {
#pragma unroll
        for (int j = 0; j < 4; j++) {
            int m0 = bm + wrow * 64 + i * 16 + g;
            int n0 = bn + wcol * 32 + j * 8 + tig * 2;
            float b0 = bias[n0], b1 = bias[n0 + 1];
            float x0 = (acc[i][j].x + b0) * scale, x1 = (acc[i][j].y + b1) * scale;
            float x2 = (acc[i][j].z + b0) * scale, x3 = (acc[i][j].w + b1) * scale;
            int b_ = m0 >> 10, hh_ = n0 >> 6, d = n0 & 63;
            if (z == 0) {
                int tt = (m0 >> 7) & 7, mr = m0 & 127;
                size_t blk = ((size_t)((b_ * 8 + tt) * 16 + hh_)) << 12;
                int addr = ((d >> 4) * 8 + (mr >> 4)) * 128
                         + ((mr & 7) * 4 + ((d >> 1) & 3)) * 4
                         + ((mr >> 3) & 1) + 2 * ((d >> 3) & 1);
                unsigned hw, lw;
                split_pair(x0, x1, hw, lw);
                qfh[blk + addr] = hw; qfl[blk + addr] = lw;
                split_pair(x2, x3, hw, lw);
                qfh[blk + addr + 1] = hw; qfl[blk + addr + 1] = lw;
            } else if (z == 1) {
                int stt = (m0 >> 6) & 15, sr = m0 & 63;
                size_t blk = ((size_t)((b_ * 16 + stt) * 16 + hh_)) << 11;
                int addr = ((d >> 4) * 8 + (sr >> 3)) * 64
                         + ((sr & 7) * 4 + ((d >> 1) & 3)) * 2 + ((d >> 3) & 1);
                unsigned hw, lw;
                split_pair(x0, x1, hw, lw);
                kfh[blk + addr] = hw; kfl[blk + addr] = lw;
                split_pair(x2, x3, hw, lw);
                kfh[blk + addr + 64] = hw; kfl[blk + addr + 64] = lw;
            } else {
                int stt = (m0 >> 6) & 15, sr = m0 & 63;
                size_t blk = ((size_t)((b_ * 16 + stt) * 16 + hh_)) << 12;
                int a00 = ((sr >> 3) * 8 + (d >> 3)) * 64
                        + ((d & 7) * 4 + (sr & 3)) * 2 + ((sr >> 2) & 1);
                vtf[blk + a00]           = f2tf32(x0);
                vtf[blk + a00 + 8]       = f2tf32(x1);
                vtf[blk + a00 + 512]     = f2tf32(x2);
                vtf[blk + a00 + 8 + 512] = f2tf32(x3);
            }
        }
    }
}

// ========== output projection GEMM (fp32 row-major out) ==========
__global__ __launch_bounds__(256, 2)
void gemm_out(const unsigned* __restrict__ ctxfh, const unsigned* __restrict__ ctxfl,
              const unsigned* __restrict__ bfh, const unsigned* __restrict__ bfl,
              const float* __restrict__ bias, float* __restrict__ o0)
{
    extern __shared__ unsigned smg[];
    const int bm = blockIdx.y * 128, bn = blockIdx.x * 128;
    const int lane = threadIdx.x & 31, warp = threadIdx.x >> 5;
    const int wrow = warp & 1, wcol = warp >> 1;

    float4 acc[4][4];
#pragma unroll
    for (int i = 0; i < 4; i++)
#pragma unroll
        for (int j = 0; j < 4; j++) acc[i][j] = make_float4(0.f, 0.f, 0.f, 0.f);

    gemm_core(ctxfh + ((size_t)(bm >> 7) << 16),
              ctxfl + ((size_t)(bm >> 7) << 16),
              bfh + ((size_t)(bn >> 7) << 16),
              bfl + ((size_t)(bn >> 7) << 16),
              smg, acc);

    const int g = lane >> 2, tig = lane & 3;
#pragma unroll
    for (int i = 0; i < 4; i++) {
#pragma unroll
        for (int j = 0; j < 4; j++) {
            int m0 = bm + wrow * 64 + i * 16 + g;
            int n0 = bn + wcol * 32 + j * 8 + tig * 2;
            float b0 = bias[n0], b1 = bias[n0 + 1];
            size_t i0 = (size_t)m0 * CC + n0, i1 = (size_t)(m0 + 8) * CC + n0;
            *(float2*)(o0 + i0) = make_float2(acc[i][j].x + b0, acc[i][j].y + b1);
            *(float2*)(o0 + i1) = make_float2(acc[i][j].z + b0, acc[i][j].w + b1);
        }
    }
}

// ============== flash attention: Q in registers, cp.async double-buffered K/V ==========
#define ZP2 66
// smem words: kf_h 2x2048, kf_l 2x2048, vf 2x4096, rf 12288, pfs 8192, Zs 128*ZP2
#define OFF_KFH 0
#define OFF_KFL 4096
#define OFF_VF  8192
#define OFF_RF  16384
#define OFF_PFS 28672
#define OFF_ZS  36864
#define FLASH6_WORDS (36864 + 128*ZP2)
#define FLASH6_SMEM (FLASH6_WORDS * 4)     // 181248 B <= 227 KB

__global__ __launch_bounds__(256)
void flash_mma6(const unsigned* __restrict__ qfh, const unsigned* __restrict__ qfl,
                const unsigned* __restrict__ qrg,
                const unsigned* __restrict__ kfh, const unsigned* __restrict__ kfl,
                const unsigned* __restrict__ vtf, const unsigned* __restrict__ rtf,
                unsigned* __restrict__ ctxfh, unsigned* __restrict__ ctxfl)
{
    extern __shared__ unsigned smu[];
    unsigned* kf_h = smu + OFF_KFH;   // [2][2048]
    unsigned* kf_l = smu + OFF_KFL;   // [2][2048]
    unsigned* vf   = smu + OFF_VF;    // [2][4096]
    unsigned* rf   = smu + OFF_RF;    // 3 ring slots x 4096
    unsigned* pfs  = smu + OFF_PFS;
    float* Zs      = (float*)(smu + OFF_ZS);
    const unsigned sbase = (unsigned)__cvta_generic_to_shared(smu);

    const int tid = threadIdx.x;
    const int lane = tid & 31;
    const int w = tid >> 5;
    const int g = lane >> 2, tig = lane & 3;
    const int b = blockIdx.y >> 4, hq = blockIdx.y & 15;
    const int bx = blockIdx.x, t0 = bx * 128;
    unsigned* pf = pfs + w * 1024;
    const int m0 = w * 16 + g, m1 = m0 + 8;

#define KV_ISSUE(i_, buf_) { \
        size_t kb_ = (size_t)((b * 16 + (i_)) * 16 + hq); \
        const unsigned* khp = kfh + (kb_ << 11); \
        const unsigned* klp = kfl + (kb_ << 11); \
        const unsigned* vp  = vtf + (kb_ << 12); \
        _Pragma("unroll") \
        for (int x = 0; x < 2; x++) { \
            CP16(sbase + (OFF_KFH + (buf_) * 2048 + (tid + 256 * x) * 4) * 4, khp + (tid + 256 * x) * 4); \
            CP16(sbase + (OFF_KFL + (buf_) * 2048 + (tid + 256 * x) * 4) * 4, klp + (tid + 256 * x) * 4); \
        } \
        _Pragma("unroll") \
        for (int x = 0; x < 4; x++) \
            CP16(sbase + (OFF_VF + (buf_) * 4096 + (tid + 256 * x) * 4) * 4, vp + (tid + 256 * x) * 4); \
    }
    KV_ISSUE(0, 0); CP_COMMIT();

    // ---- Q operands straight into registers (warp w only needs m-tile w) ----
    uint4 qh[4], ql[4], qr[8];
    {
        size_t qblk = ((size_t)((b * 8 + bx) * 16 + hq));
        const uint4* qh4 = (const uint4*)(qfh + (qblk << 12));
        const uint4* ql4 = (const uint4*)(qfl + (qblk << 12));
        const uint4* qr4 = (const uint4*)(qrg + (qblk << 13));
#pragma unroll
        for (int kb = 0; kb < 4; kb++) {
            qh[kb] = qh4[(kb * 8 + w) * 32 + lane];
            ql[kb] = ql4[(kb * 8 + w) * 32 + lane];
        }
#pragma unroll
        for (int ks = 0; ks < 8; ks++)
            qr[ks] = qr4[(ks * 8 + w) * 32 + lane];
    }

    float m_i[2] = {-1e30f, -1e30f}, l_i[2] = {0.f, 0.f};
    float4 o[8];
#pragma unroll
    for (int j = 0; j < 8; j++) o[j] = make_float4(0.f, 0.f, 0.f, 0.f);

    for (int i = 0; i < 16; i++) {
        int T = i - 2 * bx + 14;
        const int buf = i & 1;
        __syncthreads();   // prev-tile consumers done (rel slot + pf/vf reuse)

        // rel producer (synchronous; slot reuse safe after top sync)
        {
            if (i == 0) {
#pragma unroll
                for (int it = 0; it < 2; it++) {
                    const uint4* rs = (const uint4*)(rtf + (size_t)(T + it) * 4096);
                    uint4* rd = (uint4*)(rf + ((T + it) % 3) * 4096);
#pragma unroll
                    for (int x = 0; x < 4; x++) rd[tid + 256 * x] = rs[tid + 256 * x];
                }
            }
            const uint4* rs = (const uint4*)(rtf + (size_t)(T + 2) * 4096);
            uint4* rd = (uint4*)(rf + ((T + 2) % 3) * 4096);
#pragma unroll
            for (int x = 0; x < 4; x++) rd[tid + 256 * x] = rs[tid + 256 * x];
        }

        // issue K/V for tile i+1 into the other buffer (fire-and-forget)
        if (i < 15) KV_ISSUE(i + 1, buf ^ 1);
        CP_COMMIT();
        CP_WAIT1();        // tile i's K/V group complete
        __syncthreads();   // rel stores + cp.async data visible to all

        // ---- Z band mma (tf32) over 3-slot rel ring ----
        {
            const unsigned* rslot[3] = { rf + (T % 3) * 4096,
                                         rf + ((T + 1) % 3) * 4096,
                                         rf + ((T + 2) % 3) * 4096 };
            float4 zc[10];
#pragma unroll
            for (int j = 0; j < 10; j++) zc[j] = make_float4(0.f, 0.f, 0.f, 0.f);
#pragma unroll
            for (int ks = 0; ks < 8; ks++) {
#pragma unroll
                for (int j = 0; j < 10; j++) {
                    int nt = 14 - 2 * w + j;
                    uint2 bb = *(const uint2*)(rslot[nt >> 3] + (ks * 8 + (nt & 7)) * 64 + lane * 2);
                    mma_tf32(zc[j], qr[ks], bb);
                }
            }
#pragma unroll
            for (int j = 0; j < 10; j++) {
                int u = (14 - 2 * w + j) * 8 + 2 * tig;
                int s = u + m0 - 127;
                if ((unsigned)s < 64u)       Zs[m0 * ZP2 + s]     = zc[j].x;
                if ((unsigned)(s + 1) < 64u) Zs[m0 * ZP2 + s + 1] = zc[j].y;
                int s2 = s + 8;
                if ((unsigned)s2 < 64u)       Zs[m1 * ZP2 + s2]     = zc[j].z;
                if ((unsigned)(s2 + 1) < 64u) Zs[m1 * ZP2 + s2 + 1] = zc[j].w;
            }
        }
        __syncwarp();

        // ---- QK mma (3-term bf16), Q from registers ----
        const unsigned* kh_ = kf_h + buf * 2048;
        const unsigned* kl_ = kf_l + buf * 2048;
        const unsigned* vf_ = vf + buf * 4096;
        float4 sc[8];
#pragma unroll
        for (int j = 0; j < 8; j++) sc[j] = make_float4(0.f, 0.f, 0.f, 0.f);
#pragma unroll
        for (int kb = 0; kb < 4; kb++) {
#pragma unroll
            for (int nt = 0; nt < 8; nt++) {
                uint2 bh = *(const uint2*)(kh_ + (kb * 8 + nt) * 64 + lane * 2);
                uint2 bl = *(const uint2*)(kl_ + (kb * 8 + nt) * 64 + lane * 2);
                mma_bf16(sc[nt], qh[kb], bl);
                mma_bf16(sc[nt], ql[kb], bh);
                mma_bf16(sc[nt], qh[kb], bh);
            }
        }

        // ---- diag add + warp-local online softmax ----
        float v0[16], v1[16];
#pragma unroll
        for (int nt = 0; nt < 8; nt++) {
            int s = nt * 8 + 2 * tig;
            v0[2*nt]   = sc[nt].x + Zs[m0 * ZP2 + s];
            v0[2*nt+1] = sc[nt].y + Zs[m0 * ZP2 + s + 1];
            v1[2*nt]   = sc[nt].z + Zs[m1 * ZP2 + s];
            v1[2*nt+1] = sc[nt].w + Zs[m1 * ZP2 + s + 1];
        }
        float lm0 = v0[0], lm1 = v1[0];
#pragma unroll
        for (int e = 1; e < 16; e++) { lm0 = fmaxf(lm0, v0[e]); lm1 = fmaxf(lm1, v1[e]); }
        lm0 = fmaxf(lm0, __shfl_xor_sync(~0u, lm0, 1));
        lm0 = fmaxf(lm0, __shfl_xor_sync(~0u, lm0, 2));
        lm1 = fmaxf(lm1, __shfl_xor_sync(~0u, lm1, 1));
        lm1 = fmaxf(lm1, __shfl_xor_sync(~0u, lm1, 2));
        float mn0 = fmaxf(m_i[0], lm0), mn1 = fmaxf(m_i[1], lm1);
        float al0 = __expf(m_i[0] - mn0), al1 = __expf(m_i[1] - mn1);
        m_i[0] = mn0; m_i[1] = mn1;
        float rs0 = 0.f, rs1 = 0.f;
#pragma unroll
        for (int nt = 0; nt < 8; nt++) {
            int s = nt * 8 + 2 * tig;
            float p00 = __expf(v0[2*nt]   - mn0);
            float p01 = __expf(v0[2*nt+1] - mn0);
            float p10 = __expf(v1[2*nt]   - mn1);
            float p11 = __expf(v1[2*nt+1] - mn1);
            rs0 += p00 + p01; rs1 += p10 + p11;
            int base = nt * 128 + (g * 4 + (s & 3)) * 4 + 2 * ((s >> 2) & 1);
            pf[base]     = f2tf32(p00);
            pf[base + 1] = f2tf32(p10);
            pf[base + 4] = f2tf32(p01);
            pf[base + 5] = f2tf32(p11);
        }
        rs0 += __shfl_xor_sync(~0u, rs0, 1); rs0 += __shfl_xor_sync(~0u, rs0, 2);
        rs1 += __shfl_xor_sync(~0u, rs1, 1); rs1 += __shfl_xor_sync(~0u, rs1, 2);
        l_i[0] = l_i[0] * al0 + rs0;
        l_i[1] = l_i[1] * al1 + rs1;
#pragma unroll
        for (int j = 0; j < 8; j++) {
            o[j].x *= al0; o[j].y *= al0; o[j].z *= al1; o[j].w *= al1;
        }
        __syncwarp();

        // ---- PV mma (tf32): O += P @ V ----
#pragma unroll
        for (int ks = 0; ks < 8; ks++) {
            uint4 a = *(const uint4*)(pf + ks * 128 + lane * 4);
#pragma unroll
            for (int nt = 0; nt < 8; nt++) {
                uint2 bb = *(const uint2*)(vf_ + (ks * 8 + nt) * 64 + lane * 2);
                mma_tf32(o[nt], a, bb);
            }
        }
    }
#undef KV_ISSUE

    // epilogue: normalize, split, store in GEMM A-frag layout
    float inv0 = 1.f / l_i[0], inv1 = 1.f / l_i[1];
#pragma unroll
    for (int nt = 0; nt < 8; nt++) {
        int c = hq * HD + nt * 8 + 2 * tig;
        int mg0 = b * TT + t0 + m0, mg1 = b * TT + t0 + m1;
        unsigned hh, ll;
        split_pair(o[nt].x * inv0, o[nt].y * inv0, hh, ll);
        size_t a0 = afrag_addr(mg0, c);
        ctxfh[a0] = hh; ctxfl[a0] = ll;
        split_pair(o[nt].z * inv1, o[nt].w * inv1, hh, ll);
        size_t a1 = afrag_addr(mg1, c);
        ctxfh[a1] = hh; ctxfl[a1] = ll;
    }
}

// ------------------------------ launch ------------------------------
extern "C" void kernel_launch(void* const* d_in, const int* in_sizes, int n_in,
                              void* d_out, int out_size)
{
    const float* query   = (const float*)d_in[0];
    const float* key     = (const float*)d_in[1];
    const float* value   = (const float*)d_in[2];
    const float* Wq      = (const float*)d_in[3];
    const float* bq      = (const float*)d_in[4];
    const float* Wk      = (const float*)d_in[5];
    const float* bk      = (const float*)d_in[6];
    const float* Wv      = (const float*)d_in[7];
    const float* bv      = (const float*)d_in[8];
    const float* Wo      = (const float*)d_in[9];
    const float* bo      = (const float*)d_in[10];
    const float* rel_emb = (const float*)d_in[11];
    float* out = (float*)d_out;

    unsigned *afh, *afl, *bfh, *bfl, *qfh, *qfl, *kfh, *kfl, *vtf, *qrf, *rtf, *ctxfh, *ctxfl;
    cudaGetSymbolAddress((void**)&afh, g_afh);
    cudaGetSymbolAddress((void**)&afl, g_afl);
    cudaGetSymbolAddress((void**)&bfh, g_bfh);
    cudaGetSymbolAddress((void**)&bfl, g_bfl);
    cudaGetSymbolAddress((void**)&qfh, g_qfh);
    cudaGetSymbolAddress((void**)&qfl, g_qfl);
    cudaGetSymbolAddress((void**)&kfh, g_kfh);
    cudaGetSymbolAddress((void**)&kfl, g_kfl);
    cudaGetSymbolAddress((void**)&vtf, g_vtf);
    cudaGetSymbolAddress((void**)&qrf, g_qrf);
    cudaGetSymbolAddress((void**)&rtf, g_rtf);
    cudaGetSymbolAddress((void**)&ctxfh, g_ctxfh);
    cudaGetSymbolAddress((void**)&ctxfl, g_ctxfl);

    convAll<<<16896, 256>>>(query, key, value, Wq, Wk, Wv, Wo, rel_emb,
                            afh, afl, qrf, bfh, bfl, rtf);

    cudaFuncSetAttribute(gemm_qkv, cudaFuncAttributeMaxDynamicSharedMemorySize, GEMM_SMEM);
    cudaFuncSetAttribute(gemm_out, cudaFuncAttributeMaxDynamicSharedMemorySize, GEMM_SMEM);

    dim3 gqkv(CC / 128, (BB * TT) / 128, 3);
    gemm_qkv<<<gqkv, 256, GEMM_SMEM>>>(afh, afl, bfh, bfl, bq, bk, bv,
                                       qfh, qfl, kfh, kfl, vtf);

    cudaFuncSetAttribute(flash_mma6, cudaFuncAttributeMaxDynamicSharedMemorySize, FLASH6_SMEM);
    flash_mma6<<<dim3(TT / 128, BB * HH), 256, FLASH6_SMEM>>>(
        qfh, qfl, qrf, kfh, kfl, vtf, rtf, ctxfh, ctxfl);

    dim3 gout(CC / 128, (BB * TT) / 128);
    gemm_out<<<gout, 256, GEMM_SMEM>>>(ctxfh, ctxfl, bfh + 3*(size_t)(NW/2),
                                       bfl + 3*(size_t)(NW/2), bo, out);
}